// round 1
// baseline (speedup 1.0000x reference)
#include <cuda_runtime.h>
#include <math.h>

// Problem constants
#define B_  4
#define N_  512
#define D_  768
#define F_  3072
#define H_  12
#define HD_ 64
#define M_  (B_*N_)   // 2048 tokens
#define NBLOCKS 12

// ---------------- scratch (static device globals; no dynamic alloc) ----------
__device__ float g_ln[M_*D_];            // layernorm output
__device__ float g_q [M_*D_];
__device__ float g_k [M_*D_];
__device__ float g_v [M_*D_];
__device__ float g_s [B_*H_*N_*N_];      // attention scores / probs (12.58M)
__device__ float g_ff[M_*F_];            // MLP hidden

// ---------------- LayerNorm -------------------------------------------------
__global__ void ln_kernel(const float* __restrict__ x,
                          const float* __restrict__ g,
                          const float* __restrict__ be,
                          float* __restrict__ out)
{
    __shared__ float red[256];
    const int row = blockIdx.x;
    const float* xr = x + (long)row * D_;
    const int t = threadIdx.x;

    float s = 0.f;
    for (int i = t; i < D_; i += 256) s += xr[i];
    red[t] = s; __syncthreads();
    for (int o = 128; o > 0; o >>= 1) { if (t < o) red[t] += red[t+o]; __syncthreads(); }
    const float mu = red[0] * (1.0f / D_);
    __syncthreads();

    float vs = 0.f;
    for (int i = t; i < D_; i += 256) { float d = xr[i] - mu; vs += d * d; }
    red[t] = vs; __syncthreads();
    for (int o = 128; o > 0; o >>= 1) { if (t < o) red[t] += red[t+o]; __syncthreads(); }
    const float inv = rsqrtf(red[0] * (1.0f / D_) + 1e-5f);

    float* orow = out + (long)row * D_;
    for (int i = t; i < D_; i += 256)
        orow[i] = (xr[i] - mu) * inv * g[i] + be[i];
}

// ---------------- Softmax over rows of length 512 ---------------------------
__global__ void softmax_kernel(float* __restrict__ s)
{
    __shared__ float red[128];
    float* p = s + (long)blockIdx.x * N_;
    const int t = threadIdx.x;   // 128 threads, 4 elems each

    float v[4];
    float mx = -1e30f;
    #pragma unroll
    for (int i = 0; i < 4; i++) { v[i] = p[t + 128*i]; mx = fmaxf(mx, v[i]); }
    red[t] = mx; __syncthreads();
    for (int o = 64; o > 0; o >>= 1) { if (t < o) red[t] = fmaxf(red[t], red[t+o]); __syncthreads(); }
    mx = red[0]; __syncthreads();

    float sum = 0.f;
    #pragma unroll
    for (int i = 0; i < 4; i++) { v[i] = __expf(v[i] - mx); sum += v[i]; }
    red[t] = sum; __syncthreads();
    for (int o = 64; o > 0; o >>= 1) { if (t < o) red[t] += red[t+o]; __syncthreads(); }
    const float inv = 1.0f / red[0];

    #pragma unroll
    for (int i = 0; i < 4; i++) p[t + 128*i] = v[i] * inv;
}

// ---------------- Generic batched 128x128x8 fp32 GEMM -----------------------
// C = epilogue(scale * A@B + bias [, += into C])
//   TB    : B is stored N x K row-major (i.e. compute A @ B^T)
//   EPI 0 : C  = scale*acc + bias
//   EPI 1 : C  = gelu(acc + bias)          (exact gelu)
//   EPI 2 : C += acc + bias                (residual accumulate)
// blockIdx.z decomposes as z = b*H_ + h with per-operand (b,h) strides.
__device__ __forceinline__ float gelu_exact(float v) {
    return 0.5f * v * (1.0f + erff(v * 0.70710678118654752f));
}

template<bool TB, int EPI>
__global__ void __launch_bounds__(256)
sgemm(const float* __restrict__ A, const float* __restrict__ Bm,
      const float* __restrict__ bias, float* __restrict__ C,
      int M, int N, int K, int lda, int ldb, int ldc,
      long sAb, long sAh, long sBb, long sBh, long sCb, long sCh,
      float scale)
{
    const int z = blockIdx.z;
    const int zb = z / H_, zh = z % H_;
    A  += zb * sAb + zh * sAh;
    Bm += zb * sBb + zh * sBh;
    C  += zb * sCb + zh * sCh;

    __shared__ float As[8][128];
    __shared__ float Bs[8][128];

    const int tid = threadIdx.x;
    const int bm = blockIdx.y * 128, bn = blockIdx.x * 128;
    const int tx = tid & 15, ty = tid >> 4;

    float acc[8][8];
    #pragma unroll
    for (int i = 0; i < 8; i++)
        #pragma unroll
        for (int j = 0; j < 8; j++) acc[i][j] = 0.f;

    const int arow = tid >> 1;          // 0..127
    const int acol = (tid & 1) * 4;     // 0 or 4
    const int brow = tid >> 5;          // 0..7
    const int bcol = (tid & 31) * 4;    // 0..124

    for (int kt = 0; kt < K; kt += 8) {
        // A tile: rows bm..bm+127, cols kt..kt+7  (M always multiple of 128 here)
        float4 av = *(const float4*)(A + (long)(bm + arow) * lda + kt + acol);
        As[acol+0][arow] = av.x; As[acol+1][arow] = av.y;
        As[acol+2][arow] = av.z; As[acol+3][arow] = av.w;

        if (!TB) {
            float4 bv = make_float4(0.f, 0.f, 0.f, 0.f);
            if (bn + bcol < N)
                bv = *(const float4*)(Bm + (long)(kt + brow) * ldb + bn + bcol);
            *(float4*)&Bs[brow][bcol] = bv;
        } else {
            // B stored N x K: tile rows bn..bn+127, cols kt..kt+7
            float4 bv = make_float4(0.f, 0.f, 0.f, 0.f);
            if (bn + arow < N)
                bv = *(const float4*)(Bm + (long)(bn + arow) * ldb + kt + acol);
            Bs[acol+0][arow] = bv.x; Bs[acol+1][arow] = bv.y;
            Bs[acol+2][arow] = bv.z; Bs[acol+3][arow] = bv.w;
        }
        __syncthreads();

        #pragma unroll
        for (int kk = 0; kk < 8; kk++) {
            float a[8], bb[8];
            #pragma unroll
            for (int i = 0; i < 8; i++) a[i]  = As[kk][ty*8 + i];
            #pragma unroll
            for (int j = 0; j < 8; j++) bb[j] = Bs[kk][tx*8 + j];
            #pragma unroll
            for (int i = 0; i < 8; i++)
                #pragma unroll
                for (int j = 0; j < 8; j++)
                    acc[i][j] += a[i] * bb[j];
        }
        __syncthreads();
    }

    #pragma unroll
    for (int i = 0; i < 8; i++) {
        const int r = bm + ty*8 + i;
        #pragma unroll
        for (int j = 0; j < 8; j++) {
            const int c = bn + tx*8 + j;
            if (c < N) {
                float v = acc[i][j] * scale + (bias ? bias[c] : 0.f);
                const long idx = (long)r * ldc + c;
                if (EPI == 1) v = gelu_exact(v);
                if (EPI == 2) C[idx] += v;
                else          C[idx] = v;
            }
        }
    }
}

// ---------------- driver ----------------------------------------------------
extern "C" void kernel_launch(void* const* d_in, const int* in_sizes, int n_in,
                              void* d_out, int out_size)
{
    const float* x0  = (const float*)d_in[0];
    const float* Wq  = (const float*)d_in[1];
    const float* bq  = (const float*)d_in[2];
    const float* Wk  = (const float*)d_in[3];
    const float* bk  = (const float*)d_in[4];
    const float* Wv  = (const float*)d_in[5];
    const float* bv  = (const float*)d_in[6];
    const float* g1  = (const float*)d_in[7];
    const float* be1 = (const float*)d_in[8];
    const float* g2  = (const float*)d_in[9];
    const float* be2 = (const float*)d_in[10];
    const float* W0  = (const float*)d_in[11];
    const float* b0  = (const float*)d_in[12];
    const float* W1  = (const float*)d_in[13];
    const float* b1  = (const float*)d_in[14];

    float* x = (float*)d_out;   // residual stream lives in d_out

    float *ln, *q, *k, *v, *s, *ff;
    cudaGetSymbolAddress((void**)&ln, g_ln);
    cudaGetSymbolAddress((void**)&q,  g_q);
    cudaGetSymbolAddress((void**)&k,  g_k);
    cudaGetSymbolAddress((void**)&v,  g_v);
    cudaGetSymbolAddress((void**)&s,  g_s);
    cudaGetSymbolAddress((void**)&ff, g_ff);

    cudaMemcpyAsync(x, x0, sizeof(float)*M_*D_, cudaMemcpyDeviceToDevice);

    const long sQb = (long)N_*D_;      // batch stride in q/k/v/x
    const long sSb = (long)H_*N_*N_;   // batch stride in scores
    const long sSh = (long)N_*N_;      // head stride in scores

    for (int blk = 0; blk < NBLOCKS; blk++) {
        // ---- attention ----
        ln_kernel<<<M_, 256>>>(x, g1, be1, ln);

        dim3 gqkv(D_/128, M_/128, 1);
        sgemm<false,0><<<gqkv,256>>>(ln, Wq, bq, q, M_, D_, D_, D_, D_, D_,
                                     0,0,0,0,0,0, 1.f);
        sgemm<false,0><<<gqkv,256>>>(ln, Wk, bk, k, M_, D_, D_, D_, D_, D_,
                                     0,0,0,0,0,0, 1.f);
        sgemm<false,0><<<gqkv,256>>>(ln, Wv, bv, v, M_, D_, D_, D_, D_, D_,
                                     0,0,0,0,0,0, 1.f);

        // scores[b,h] = (q_h @ k_h^T) / sqrt(64)
        dim3 gs(N_/128, N_/128, B_*H_);
        sgemm<true,0><<<gs,256>>>(q, k, nullptr, s, N_, N_, HD_, D_, D_, N_,
                                  sQb, HD_, sQb, HD_, sSb, sSh, 0.125f);

        softmax_kernel<<<B_*H_*N_, 128>>>(s);

        // x += probs @ v   (residual fused into epilogue)
        dim3 ga(1, N_/128, B_*H_);
        sgemm<false,2><<<ga,256>>>(s, v, nullptr, x, N_, HD_, N_, N_, D_, D_,
                                   sSb, sSh, sQb, HD_, sQb, HD_, 1.f);

        // ---- MLP ----
        ln_kernel<<<M_, 256>>>(x, g2, be2, ln);

        dim3 g0(F_/128, M_/128, 1);
        sgemm<false,1><<<g0,256>>>(ln, W0, b0, ff, M_, F_, D_, D_, F_, F_,
                                   0,0,0,0,0,0, 1.f);

        dim3 g1g(D_/128, M_/128, 1);
        sgemm<false,2><<<g1g,256>>>(ff, W1, b1, x, M_, D_, F_, F_, D_, D_,
                                    0,0,0,0,0,0, 1.f);
    }
    (void)in_sizes; (void)n_in; (void)out_size;
}

// round 3
// speedup vs baseline: 2.7778x; 2.7778x over previous
#include <cuda_runtime.h>
#include <cuda_bf16.h>
#include <math.h>
#include <stdint.h>

// Problem constants
#define B_  4
#define N_  512
#define D_  768
#define F_  3072
#define H_  12
#define HD_ 64
#define M_  (B_*N_)   // 2048 tokens
#define NBLOCKS 12

// =================== scratch (static device globals) ========================
__device__ float g_v[M_*D_];                         // V pre-transpose (fp32)
__device__ float g_s[(long)B_*H_*N_*N_];             // attention scores (fp32)
// split-bf16 planes: [hi plane][lo plane], plane offset = element count
__device__ __align__(256) __nv_bfloat16 g_lns[2L*M_*D_];
__device__ __align__(256) __nv_bfloat16 g_qs [2L*M_*D_];
__device__ __align__(256) __nv_bfloat16 g_ks [2L*M_*D_];
__device__ __align__(256) __nv_bfloat16 g_vts[2L*B_*H_*HD_*N_];
__device__ __align__(256) __nv_bfloat16 g_ps [2L*B_*H_*N_*N_];
__device__ __align__(256) __nv_bfloat16 g_ffs[2L*M_*F_];
__device__ __align__(256) __nv_bfloat16 g_wqt[2L*D_*D_];
__device__ __align__(256) __nv_bfloat16 g_wkt[2L*D_*D_];
__device__ __align__(256) __nv_bfloat16 g_wvt[2L*D_*D_];
__device__ __align__(256) __nv_bfloat16 g_w0t[2L*D_*F_];
__device__ __align__(256) __nv_bfloat16 g_w1t[2L*D_*F_];

// =================== PTX helpers ===========================================
__device__ __forceinline__ uint32_t smem_u32(const void* p){
    uint32_t a;
    asm("{ .reg .u64 t; cvta.to.shared.u64 t, %1; cvt.u32.u64 %0, t; }" : "=r"(a) : "l"(p));
    return a;
}
__device__ __forceinline__ void cpa16(uint32_t d, const void* s){
    asm volatile("cp.async.cg.shared.global [%0], [%1], 16;" :: "r"(d), "l"(s));
}
#define CP_COMMIT() asm volatile("cp.async.commit_group;" ::: "memory")

__device__ __forceinline__ void ldsm4(uint32_t* r, uint32_t addr){
    asm volatile("ldmatrix.sync.aligned.m8n8.x4.shared.b16 {%0,%1,%2,%3}, [%4];"
                 : "=r"(r[0]), "=r"(r[1]), "=r"(r[2]), "=r"(r[3]) : "r"(addr));
}
__device__ __forceinline__ void mma16816(float* c, const uint32_t* a, const uint32_t* b){
    asm volatile(
        "mma.sync.aligned.m16n8k16.row.col.f32.bf16.bf16.f32 "
        "{%0,%1,%2,%3}, {%4,%5,%6,%7}, {%8,%9}, {%0,%1,%2,%3};"
        : "+f"(c[0]), "+f"(c[1]), "+f"(c[2]), "+f"(c[3])
        : "r"(a[0]), "r"(a[1]), "r"(a[2]), "r"(a[3]), "r"(b[0]), "r"(b[1]));
}
__device__ __forceinline__ float gelu_exact(float v){
    return 0.5f * v * (1.0f + erff(v * 0.70710678118654752f));
}
__device__ __forceinline__ uint32_t swz(uint32_t off){ return off ^ ((off >> 3) & 0x70); }

// =================== LayerNorm (emits split-bf16 planes) ====================
__global__ void ln_kernel(const float* __restrict__ x,
                          const float* __restrict__ g,
                          const float* __restrict__ be,
                          __nv_bfloat16* __restrict__ out, long plane)
{
    __shared__ float red[256];
    const int row = blockIdx.x;
    const float* xr = x + (long)row * D_;
    const int t = threadIdx.x;

    float s = 0.f;
    for (int i = t; i < D_; i += 256) s += xr[i];
    red[t] = s; __syncthreads();
    for (int o = 128; o > 0; o >>= 1) { if (t < o) red[t] += red[t+o]; __syncthreads(); }
    const float mu = red[0] * (1.0f / D_);
    __syncthreads();

    float vs = 0.f;
    for (int i = t; i < D_; i += 256) { float d = xr[i] - mu; vs += d * d; }
    red[t] = vs; __syncthreads();
    for (int o = 128; o > 0; o >>= 1) { if (t < o) red[t] += red[t+o]; __syncthreads(); }
    const float inv = rsqrtf(red[0] * (1.0f / D_) + 1e-5f);

    __nv_bfloat16* orow = out + (long)row * D_;
    for (int i = t; i < D_; i += 256) {
        float v = (xr[i] - mu) * inv * g[i] + be[i];
        __nv_bfloat16 h = __float2bfloat16(v);
        orow[i] = h;
        orow[plane + i] = __float2bfloat16(v - __bfloat162float(h));
    }
}

// =================== Softmax (fp32 in, split-bf16 out) ======================
__global__ void softmax_kernel(const float* __restrict__ s,
                               __nv_bfloat16* __restrict__ out, long plane)
{
    __shared__ float red[128];
    const float* p = s + (long)blockIdx.x * N_;
    __nv_bfloat16* o = out + (long)blockIdx.x * N_;
    const int t = threadIdx.x;

    float v[4];
    float mx = -1e30f;
    #pragma unroll
    for (int i = 0; i < 4; i++) { v[i] = p[t + 128*i]; mx = fmaxf(mx, v[i]); }
    red[t] = mx; __syncthreads();
    for (int o2 = 64; o2 > 0; o2 >>= 1) { if (t < o2) red[t] = fmaxf(red[t], red[t+o2]); __syncthreads(); }
    mx = red[0]; __syncthreads();

    float sum = 0.f;
    #pragma unroll
    for (int i = 0; i < 4; i++) { v[i] = __expf(v[i] - mx); sum += v[i]; }
    red[t] = sum; __syncthreads();
    for (int o2 = 64; o2 > 0; o2 >>= 1) { if (t < o2) red[t] += red[t+o2]; __syncthreads(); }
    const float inv = 1.0f / red[0];

    #pragma unroll
    for (int i = 0; i < 4; i++) {
        float w = v[i] * inv;
        __nv_bfloat16 h = __float2bfloat16(w);
        o[t + 128*i] = h;
        o[plane + t + 128*i] = __float2bfloat16(w - __bfloat162float(h));
    }
}

// =================== Tiled transpose + split ===============================
// in[r, c] (row stride ldin) -> out[c*ldout + r] as hi/lo planes
__global__ void tsplit_kernel(const float* __restrict__ in, __nv_bfloat16* __restrict__ out,
                              int ldin, int ldout, long inZb, long inZh, long outZ, long plane)
{
    __shared__ float t[32][33];
    const int z = blockIdx.z;
    in  += (long)(z / H_) * inZb + (long)(z % H_) * inZh;
    out += (long)z * outZ;
    const int c0 = blockIdx.x * 32, r0 = blockIdx.y * 32;
    const int tx = threadIdx.x, ty = threadIdx.y;
    #pragma unroll
    for (int i = 0; i < 32; i += 8)
        t[ty+i][tx] = in[(long)(r0+ty+i) * ldin + c0 + tx];
    __syncthreads();
    #pragma unroll
    for (int i = 0; i < 32; i += 8) {
        float v = t[tx][ty+i];
        __nv_bfloat16 h = __float2bfloat16(v);
        long o = (long)(c0+ty+i) * ldout + r0 + tx;
        out[o] = h;
        out[o + plane] = __float2bfloat16(v - __bfloat162float(h));
    }
}

// =================== HMMA (mma.sync) GEMM ==================================
// D[M,N] = epilogue(scale * A @ B^T + bias). A: [M,K] K-major split planes.
// B: [N,K] K-major split planes. 3 passes: hi*hi, hi*lo, lo*hi (fp32 accum).
// CTA tile 128 x TN, BK=64 bf16 (128B rows, SW128 swizzle), double buffered.
// 8 warps: 4 (M) x 2 (N); warp tile 32 x (TN/2).
// EPI 0: fp32 C  = v*scale + bias
// EPI 2: fp32 C += v*scale + bias           (residual)
// EPI 3: split-bf16 C = v*scale + bias
// EPI 4: split-bf16 C = gelu(v + bias)
template<int TN, int EPI>
__global__ void __launch_bounds__(256)
gemm_mma(const __nv_bfloat16* __restrict__ A, const __nv_bfloat16* __restrict__ B,
         const float* __restrict__ bias, void* __restrict__ Cv,
         int K, int lda, int ldb, int ldc,
         long planeA, long planeB, long planeC,
         long sAb, long sAh, long sBb, long sBh, long sCb, long sCh,
         float scale)
{
    extern __shared__ char sm[];
    constexpr int ABYTES = 128 * 128;          // 128 rows x 64 bf16
    constexpr int BBYTES = TN * 128;
    constexpr int STG = ABYTES + BBYTES;
    constexpr int WN  = TN / 2;                // warp N extent
    constexpr int NF  = WN / 8;                // n8 frags per warp

    const uint32_t sb0 = smem_u32(sm);
    const uint32_t smb = (sb0 + 127) & ~127u;

    const int tid = threadIdx.x;
    const int wid = tid >> 5, l = tid & 31;
    const int wm = (wid & 3) * 32;
    const int wn = (wid >> 2) * WN;

    const int z = blockIdx.z, zb = z / H_, zh = z % H_;
    const long bm = (long)blockIdx.y * 128;
    const long bn = (long)blockIdx.x * TN;

    A += zb * sAb + zh * sAh;
    B += zb * sBb + zh * sBh;
    float* Cf = (float*)Cv + zb * sCb + zh * sCh;
    __nv_bfloat16* Cb = (__nv_bfloat16*)Cv + zb * sCb + zh * sCh;

    const int kch = K / 64;
    const int NC = 3 * kch;

    float acc[2][NF][4];
    #pragma unroll
    for (int i = 0; i < 2; i++)
        #pragma unroll
        for (int j = 0; j < NF; j++)
            #pragma unroll
            for (int q = 0; q < 4; q++) acc[i][j][q] = 0.f;

    auto load_chunk = [&](int c, int st) {
        const int p  = c / kch;
        const int kk = (c - p * kch) * 64;
        const __nv_bfloat16* Ap = A + ((p == 2) ? planeA : 0) + kk;
        const __nv_bfloat16* Bp = B + ((p == 1) ? planeB : 0) + kk;
        const uint32_t sA = smb + st * STG;
        const uint32_t sB = sA + ABYTES;
        #pragma unroll
        for (int j = 0; j < 4; j++) {
            int idx = tid * 4 + j;                 // 0..1023
            int row = idx >> 3, c16 = (idx & 7) * 16;
            cpa16(sA + swz(row * 128 + c16),
                  (const char*)(Ap + (bm + row) * lda) + c16);
        }
        constexpr int BCH = (TN * 128) / (256 * 16);   // 4 (TN=128) / 2 (TN=64)
        #pragma unroll
        for (int j = 0; j < BCH; j++) {
            int idx = tid * BCH + j;
            int row = idx >> 3, c16 = (idx & 7) * 16;
            cpa16(sB + swz(row * 128 + c16),
                  (const char*)(Bp + (bn + row) * ldb) + c16);
        }
        CP_COMMIT();
    };

    auto compute = [&](int st) {
        const uint32_t bA = smb + st * STG;
        const uint32_t bB = bA + ABYTES;
        #pragma unroll
        for (int kk2 = 0; kk2 < 4; kk2++) {
            uint32_t a[2][4];
            #pragma unroll
            for (int tm = 0; tm < 2; tm++) {
                int row = wm + tm * 16 + (l & 15);
                uint32_t off = row * 128 + kk2 * 32 + ((l >> 4) * 16);
                ldsm4(a[tm], bA + swz(off));
            }
            #pragma unroll
            for (int nb = 0; nb < NF / 2; nb++) {
                uint32_t b[4];
                int rowB = wn + nb * 16 + (l & 7) + ((l >> 4) << 3);
                uint32_t off = rowB * 128 + kk2 * 32 + (((l >> 3) & 1) * 16);
                ldsm4(b, bB + swz(off));
                #pragma unroll
                for (int tm = 0; tm < 2; tm++) {
                    mma16816(acc[tm][2*nb],   a[tm], b);
                    mma16816(acc[tm][2*nb+1], a[tm], b + 2);
                }
            }
        }
    };

    load_chunk(0, 0);
    for (int c = 0; c < NC; c++) {
        if (c + 1 < NC) {
            load_chunk(c + 1, (c + 1) & 1);
            asm volatile("cp.async.wait_group 1;" ::: "memory");
        } else {
            asm volatile("cp.async.wait_group 0;" ::: "memory");
        }
        __syncthreads();
        compute(c & 1);
        __syncthreads();
    }

    // -------- epilogue straight from registers --------
    #pragma unroll
    for (int tm = 0; tm < 2; tm++) {
        #pragma unroll
        for (int nf = 0; nf < NF; nf++) {
            const long col = bn + wn + nf * 8 + (l & 3) * 2;
            const float bb0 = bias ? bias[col]     : 0.f;
            const float bb1 = bias ? bias[col + 1] : 0.f;
            #pragma unroll
            for (int h = 0; h < 2; h++) {
                const long row = bm + wm + tm * 16 + (l >> 2) + h * 8;
                float v0 = acc[tm][nf][2*h]     * scale + bb0;
                float v1 = acc[tm][nf][2*h + 1] * scale + bb1;
                if (EPI == 4) { v0 = gelu_exact(v0); v1 = gelu_exact(v1); }
                const long idx = row * (long)ldc + col;
                if (EPI == 0) {
                    float2 t; t.x = v0; t.y = v1;
                    *(float2*)(Cf + idx) = t;
                } else if (EPI == 2) {
                    float2 t = *(float2*)(Cf + idx);
                    t.x += v0; t.y += v1;
                    *(float2*)(Cf + idx) = t;
                } else {   // 3 / 4: split-bf16 planes
                    __nv_bfloat16 h0 = __float2bfloat16(v0);
                    __nv_bfloat16 h1 = __float2bfloat16(v1);
                    __nv_bfloat162 hv; hv.x = h0; hv.y = h1;
                    *(__nv_bfloat162*)(Cb + idx) = hv;
                    __nv_bfloat162 lv;
                    lv.x = __float2bfloat16(v0 - __bfloat162float(h0));
                    lv.y = __float2bfloat16(v1 - __bfloat162float(h1));
                    *(__nv_bfloat162*)(Cb + idx + planeC) = lv;
                }
            }
        }
    }
}

// =================== driver ================================================
extern "C" void kernel_launch(void* const* d_in, const int* in_sizes, int n_in,
                              void* d_out, int out_size)
{
    const float* x0  = (const float*)d_in[0];
    const float* Wq  = (const float*)d_in[1];
    const float* bq  = (const float*)d_in[2];
    const float* Wk  = (const float*)d_in[3];
    const float* bk  = (const float*)d_in[4];
    const float* Wv  = (const float*)d_in[5];
    const float* bv  = (const float*)d_in[6];
    const float* g1  = (const float*)d_in[7];
    const float* be1 = (const float*)d_in[8];
    const float* g2  = (const float*)d_in[9];
    const float* be2 = (const float*)d_in[10];
    const float* W0  = (const float*)d_in[11];
    const float* b0  = (const float*)d_in[12];
    const float* W1  = (const float*)d_in[13];
    const float* b1  = (const float*)d_in[14];

    float* x = (float*)d_out;

    float *vf, *s;
    __nv_bfloat16 *lns, *qs, *ks, *vts, *ps, *ffs, *wqt, *wkt, *wvt, *w0t, *w1t;
    cudaGetSymbolAddress((void**)&vf,  g_v);
    cudaGetSymbolAddress((void**)&s,   g_s);
    cudaGetSymbolAddress((void**)&lns, g_lns);
    cudaGetSymbolAddress((void**)&qs,  g_qs);
    cudaGetSymbolAddress((void**)&ks,  g_ks);
    cudaGetSymbolAddress((void**)&vts, g_vts);
    cudaGetSymbolAddress((void**)&ps,  g_ps);
    cudaGetSymbolAddress((void**)&ffs, g_ffs);
    cudaGetSymbolAddress((void**)&wqt, g_wqt);
    cudaGetSymbolAddress((void**)&wkt, g_wkt);
    cudaGetSymbolAddress((void**)&wvt, g_wvt);
    cudaGetSymbolAddress((void**)&w0t, g_w0t);
    cudaGetSymbolAddress((void**)&w1t, g_w1t);

    const int SM128 = 2*(128*128 + 128*128) + 256;   // 65792
    const int SM64  = 2*(128*128 +  64*128) + 256;   // 49408
    cudaFuncSetAttribute(gemm_mma<128,0>, cudaFuncAttributeMaxDynamicSharedMemorySize, SM128);
    cudaFuncSetAttribute(gemm_mma<128,2>, cudaFuncAttributeMaxDynamicSharedMemorySize, SM128);
    cudaFuncSetAttribute(gemm_mma<128,3>, cudaFuncAttributeMaxDynamicSharedMemorySize, SM128);
    cudaFuncSetAttribute(gemm_mma<128,4>, cudaFuncAttributeMaxDynamicSharedMemorySize, SM128);
    cudaFuncSetAttribute(gemm_mma<64,2>,  cudaFuncAttributeMaxDynamicSharedMemorySize, SM64);

    cudaMemcpyAsync(x, x0, sizeof(float)*M_*D_, cudaMemcpyDeviceToDevice);

    // ---- weight preprocessing: transpose + split (once per launch) ----
    dim3 tb(32, 8);
    tsplit_kernel<<<dim3(D_/32, D_/32, 1), tb>>>(Wq, wqt, D_, D_, 0,0,0, (long)D_*D_);
    tsplit_kernel<<<dim3(D_/32, D_/32, 1), tb>>>(Wk, wkt, D_, D_, 0,0,0, (long)D_*D_);
    tsplit_kernel<<<dim3(D_/32, D_/32, 1), tb>>>(Wv, wvt, D_, D_, 0,0,0, (long)D_*D_);
    tsplit_kernel<<<dim3(F_/32, D_/32, 1), tb>>>(W0, w0t, F_, D_, 0,0,0, (long)D_*F_);
    tsplit_kernel<<<dim3(D_/32, F_/32, 1), tb>>>(W1, w1t, D_, F_, 0,0,0, (long)D_*F_);

    const long MD  = (long)M_ * D_;
    const long MF  = (long)M_ * F_;
    const long WDD = (long)D_ * D_;
    const long WDF = (long)D_ * F_;
    const long SP  = (long)B_ * H_ * N_ * N_;     // scores elements
    const long VTP = (long)B_ * H_ * HD_ * N_;    // v^T elements
    const long sXb = (long)N_ * D_;               // batch stride in token-major tensors
    const long sSb = (long)H_ * N_ * N_;
    const long sSh = (long)N_ * N_;

    for (int blk = 0; blk < NBLOCKS; blk++) {
        // ---- attention ----
        ln_kernel<<<M_, 256>>>(x, g1, be1, lns, MD);

        dim3 gqkv(D_/128, M_/128, 1);
        gemm_mma<128,3><<<gqkv, 256, SM128>>>(lns, wqt, bq, qs, D_, D_, D_, D_,
                                              MD, WDD, MD, 0,0,0,0,0,0, 1.f);
        gemm_mma<128,3><<<gqkv, 256, SM128>>>(lns, wkt, bk, ks, D_, D_, D_, D_,
                                              MD, WDD, MD, 0,0,0,0,0,0, 1.f);
        gemm_mma<128,0><<<gqkv, 256, SM128>>>(lns, wvt, bv, vf, D_, D_, D_, D_,
                                              MD, WDD, 0, 0,0,0,0,0,0, 1.f);

        // v: per-head transpose+split -> vts[z][64][512]
        tsplit_kernel<<<dim3(HD_/32, N_/32, B_*H_), tb>>>(
            vf, vts, D_, N_, (long)N_*D_, (long)HD_, (long)HD_*N_, VTP);

        // scores[b,h] = (q_h @ k_h^T) / 8
        dim3 gs(N_/128, N_/128, B_*H_);
        gemm_mma<128,0><<<gs, 256, SM128>>>(qs, ks, nullptr, s, HD_, D_, D_, N_,
                                            MD, MD, 0,
                                            sXb, HD_, sXb, HD_, sSb, sSh, 0.125f);

        softmax_kernel<<<B_*H_*N_, 128>>>(s, ps, SP);

        // x += probs @ v
        dim3 ga(1, N_/128, B_*H_);
        gemm_mma<64,2><<<ga, 256, SM64>>>(ps, vts, nullptr, x, N_, N_, N_, D_,
                                          SP, VTP, 0,
                                          sSb, sSh, (long)H_*HD_*N_, (long)HD_*N_,
                                          sXb, HD_, 1.f);

        // ---- MLP ----
        ln_kernel<<<M_, 256>>>(x, g2, be2, lns, MD);

        dim3 g0(F_/128, M_/128, 1);
        gemm_mma<128,4><<<g0, 256, SM128>>>(lns, w0t, b0, ffs, D_, D_, D_, F_,
                                            MD, WDF, MF, 0,0,0,0,0,0, 1.f);

        dim3 g1g(D_/128, M_/128, 1);
        gemm_mma<128,2><<<g1g, 256, SM128>>>(ffs, w1t, b1, x, F_, F_, F_, D_,
                                             MF, WDF, 0, 0,0,0,0,0,0, 1.f);
    }
    (void)in_sizes; (void)n_in; (void)out_size;
}

// round 4
// speedup vs baseline: 3.3392x; 1.2021x over previous
#include <cuda_runtime.h>
#include <cuda_bf16.h>
#include <math.h>
#include <stdint.h>

// Problem constants
#define B_  4
#define N_  512
#define D_  768
#define F_  3072
#define H_  12
#define HD_ 64
#define M_  (B_*N_)   // 2048 tokens
#define NBLOCKS 12
#define QKVN (3*D_)   // 2304

// =================== scratch (static device globals) ========================
// split-bf16 planes: [hi plane][lo plane], plane offset = element count
__device__ __align__(256) __nv_bfloat16 g_lns [2L*M_*D_];
__device__ __align__(256) __nv_bfloat16 g_qkvs[2L*M_*QKVN];
__device__ __align__(256) __nv_bfloat16 g_vts [2L*B_*H_*HD_*N_];
__device__ __align__(256) __nv_bfloat16 g_ffs [2L*M_*F_];
__device__ __align__(256) __nv_bfloat16 g_wqkv[2L*QKVN*D_];
__device__ __align__(256) __nv_bfloat16 g_w0t [2L*D_*F_];
__device__ __align__(256) __nv_bfloat16 g_w1t [2L*D_*F_];
__device__ float g_bqkv[QKVN];

// =================== PTX helpers ===========================================
__device__ __forceinline__ uint32_t smem_u32(const void* p){
    uint32_t a;
    asm("{ .reg .u64 t; cvta.to.shared.u64 t, %1; cvt.u32.u64 %0, t; }" : "=r"(a) : "l"(p));
    return a;
}
__device__ __forceinline__ void cpa16(uint32_t d, const void* s){
    asm volatile("cp.async.cg.shared.global [%0], [%1], 16;" :: "r"(d), "l"(s));
}
#define CP_COMMIT() asm volatile("cp.async.commit_group;" ::: "memory")

__device__ __forceinline__ void ldsm4(uint32_t* r, uint32_t addr){
    asm volatile("ldmatrix.sync.aligned.m8n8.x4.shared.b16 {%0,%1,%2,%3}, [%4];"
                 : "=r"(r[0]), "=r"(r[1]), "=r"(r[2]), "=r"(r[3]) : "r"(addr));
}
__device__ __forceinline__ void mma16816(float* c, const uint32_t* a, const uint32_t* b){
    asm volatile(
        "mma.sync.aligned.m16n8k16.row.col.f32.bf16.bf16.f32 "
        "{%0,%1,%2,%3}, {%4,%5,%6,%7}, {%8,%9}, {%0,%1,%2,%3};"
        : "+f"(c[0]), "+f"(c[1]), "+f"(c[2]), "+f"(c[3])
        : "r"(a[0]), "r"(a[1]), "r"(a[2]), "r"(a[3]), "r"(b[0]), "r"(b[1]));
}
__device__ __forceinline__ float gelu_exact(float v){
    return 0.5f * v * (1.0f + erff(v * 0.70710678118654752f));
}
__device__ __forceinline__ uint32_t swz(uint32_t off){ return off ^ ((off >> 3) & 0x70); }
__device__ __forceinline__ uint32_t pkh(float x, float y){
    __nv_bfloat162 h; h.x = __float2bfloat16(x); h.y = __float2bfloat16(y);
    return *(uint32_t*)&h;
}
__device__ __forceinline__ uint32_t pkl(float x, float y){
    float rx = x - __bfloat162float(__float2bfloat16(x));
    float ry = y - __bfloat162float(__float2bfloat16(y));
    __nv_bfloat162 h; h.x = __float2bfloat16(rx); h.y = __float2bfloat16(ry);
    return *(uint32_t*)&h;
}

// =================== LayerNorm (emits split-bf16 planes) ====================
__global__ void ln_kernel(const float* __restrict__ x,
                          const float* __restrict__ g,
                          const float* __restrict__ be,
                          __nv_bfloat16* __restrict__ out, long plane)
{
    __shared__ float red[256];
    const int row = blockIdx.x;
    const float* xr = x + (long)row * D_;
    const int t = threadIdx.x;

    float s = 0.f;
    for (int i = t; i < D_; i += 256) s += xr[i];
    red[t] = s; __syncthreads();
    for (int o = 128; o > 0; o >>= 1) { if (t < o) red[t] += red[t+o]; __syncthreads(); }
    const float mu = red[0] * (1.0f / D_);
    __syncthreads();

    float vs = 0.f;
    for (int i = t; i < D_; i += 256) { float d = xr[i] - mu; vs += d * d; }
    red[t] = vs; __syncthreads();
    for (int o = 128; o > 0; o >>= 1) { if (t < o) red[t] += red[t+o]; __syncthreads(); }
    const float inv = rsqrtf(red[0] * (1.0f / D_) + 1e-5f);

    __nv_bfloat16* orow = out + (long)row * D_;
    for (int i = t; i < D_; i += 256) {
        float v = (xr[i] - mu) * inv * g[i] + be[i];
        __nv_bfloat16 h = __float2bfloat16(v);
        orow[i] = h;
        orow[plane + i] = __float2bfloat16(v - __bfloat162float(h));
    }
}

// =================== Weight transpose + split (fp32 in) =====================
__global__ void tsplit_kernel(const float* __restrict__ in, __nv_bfloat16* __restrict__ out,
                              int ldin, int ldout, long plane)
{
    __shared__ float t[32][33];
    const int c0 = blockIdx.x * 32, r0 = blockIdx.y * 32;
    const int tx = threadIdx.x, ty = threadIdx.y;
    #pragma unroll
    for (int i = 0; i < 32; i += 8)
        t[ty+i][tx] = in[(long)(r0+ty+i) * ldin + c0 + tx];
    __syncthreads();
    #pragma unroll
    for (int i = 0; i < 32; i += 8) {
        float v = t[tx][ty+i];
        __nv_bfloat16 h = __float2bfloat16(v);
        long o = (long)(c0+ty+i) * ldout + r0 + tx;
        out[o] = h;
        out[o + plane] = __float2bfloat16(v - __bfloat162float(h));
    }
}

__global__ void cat_bias(const float* __restrict__ a, const float* __restrict__ k,
                         const float* __restrict__ v, float* __restrict__ o)
{
    int i = blockIdx.x * 256 + threadIdx.x;
    if (i < QKVN)
        o[i] = (i < D_) ? a[i] : (i < 2*D_) ? k[i - D_] : v[i - 2*D_];
}

// =================== V^T per head (bf16 planes) =============================
// in: qkvs planes [M, 2304], V at col 1536 + h*64. out: vts planes [z][64][512]
__global__ void vtrans(const __nv_bfloat16* __restrict__ qkv, __nv_bfloat16* __restrict__ vt,
                       long planeIn, long planeOut)
{
    __shared__ __nv_bfloat16 t0[32][33], t1[32][33];
    const int z = blockIdx.z, b = z / H_, h = z % H_;
    const int hd0 = blockIdx.x * 32, n0 = blockIdx.y * 32;
    const int tx = threadIdx.x, ty = threadIdx.y;
    #pragma unroll
    for (int i = 0; i < 32; i += 8) {
        long src = (long)(b*N_ + n0 + ty + i) * QKVN + 2*D_ + h*HD_ + hd0 + tx;
        t0[ty+i][tx] = qkv[src];
        t1[ty+i][tx] = qkv[src + planeIn];
    }
    __syncthreads();
    #pragma unroll
    for (int i = 0; i < 32; i += 8) {
        long dst = (long)z*HD_*N_ + (long)(hd0+ty+i)*N_ + n0 + tx;
        vt[dst] = t0[tx][ty+i];
        vt[dst + planeOut] = t1[tx][ty+i];
    }
}

// =================== HMMA GEMM, 3-stage pipeline ===========================
// D[M,N] = epilogue(A @ B^T + bias). Split planes, 3 passes (hi.hi, hi.lo, lo.hi).
// CTA 128x128, BK=64, 8 warps 4x2, warp tile 32x64.
// EPI 2: fp32 C += v + bias (residual) | EPI 3: split-bf16 C = v + bias
// EPI 4: split-bf16 C = gelu(v + bias)
template<int EPI>
__global__ void __launch_bounds__(256)
gemm_mma(const __nv_bfloat16* __restrict__ A, const __nv_bfloat16* __restrict__ B,
         const float* __restrict__ bias, void* __restrict__ Cv,
         int K, int lda, int ldb, int ldc,
         long planeA, long planeB, long planeC)
{
    extern __shared__ char sm[];
    constexpr int ABYTES = 128 * 128;
    constexpr int BBYTES = 128 * 128;
    constexpr int STG = ABYTES + BBYTES;

    const uint32_t smb = (smem_u32(sm) + 127) & ~127u;

    const int tid = threadIdx.x;
    const int wid = tid >> 5, l = tid & 31;
    const int wm = (wid & 3) * 32;
    const int wn = (wid >> 2) * 64;

    const long bm = (long)blockIdx.y * 128;
    const long bn = (long)blockIdx.x * 128;

    float* Cf = (float*)Cv;
    __nv_bfloat16* Cb = (__nv_bfloat16*)Cv;

    const int kch = K / 64;
    const int NC = 3 * kch;

    float acc[2][8][4];
    #pragma unroll
    for (int i = 0; i < 2; i++)
        #pragma unroll
        for (int j = 0; j < 8; j++)
            #pragma unroll
            for (int q = 0; q < 4; q++) acc[i][j][q] = 0.f;

    auto load_chunk = [&](int c, int st) {
        const int p  = c / kch;
        const int kk = (c - p * kch) * 64;
        const __nv_bfloat16* Ap = A + ((p == 2) ? planeA : 0) + kk;
        const __nv_bfloat16* Bp = B + ((p == 1) ? planeB : 0) + kk;
        const uint32_t sA = smb + st * STG;
        const uint32_t sB = sA + ABYTES;
        #pragma unroll
        for (int j = 0; j < 4; j++) {
            int idx = tid * 4 + j;
            int row = idx >> 3, c16 = (idx & 7) * 16;
            cpa16(sA + swz(row * 128 + c16),
                  (const char*)(Ap + (bm + row) * lda) + c16);
        }
        #pragma unroll
        for (int j = 0; j < 4; j++) {
            int idx = tid * 4 + j;
            int row = idx >> 3, c16 = (idx & 7) * 16;
            cpa16(sB + swz(row * 128 + c16),
                  (const char*)(Bp + (bn + row) * ldb) + c16);
        }
        CP_COMMIT();
    };

    auto compute = [&](int st) {
        const uint32_t bA = smb + st * STG;
        const uint32_t bB = bA + ABYTES;
        #pragma unroll
        for (int kk2 = 0; kk2 < 4; kk2++) {
            uint32_t a[2][4];
            #pragma unroll
            for (int tm = 0; tm < 2; tm++) {
                int row = wm + tm * 16 + (l & 15);
                uint32_t off = row * 128 + kk2 * 32 + ((l >> 4) * 16);
                ldsm4(a[tm], bA + swz(off));
            }
            #pragma unroll
            for (int nb = 0; nb < 4; nb++) {
                uint32_t b[4];
                int rowB = wn + nb * 16 + (l & 7) + ((l >> 4) << 3);
                uint32_t off = rowB * 128 + kk2 * 32 + (((l >> 3) & 1) * 16);
                ldsm4(b, bB + swz(off));
                #pragma unroll
                for (int tm = 0; tm < 2; tm++) {
                    mma16816(acc[tm][2*nb],   a[tm], b);
                    mma16816(acc[tm][2*nb+1], a[tm], b + 2);
                }
            }
        }
    };

    load_chunk(0, 0);
    load_chunk(1, 1);
    for (int c = 0; c < NC; c++) {
        if (c < NC - 1) asm volatile("cp.async.wait_group 1;" ::: "memory");
        else            asm volatile("cp.async.wait_group 0;" ::: "memory");
        __syncthreads();
        if (c + 2 < NC) load_chunk(c + 2, (c + 2) % 3);
        compute(c % 3);
    }

    // -------- epilogue --------
    #pragma unroll
    for (int tm = 0; tm < 2; tm++) {
        #pragma unroll
        for (int nf = 0; nf < 8; nf++) {
            const long col = bn + wn + nf * 8 + (l & 3) * 2;
            const float bb0 = bias ? bias[col]     : 0.f;
            const float bb1 = bias ? bias[col + 1] : 0.f;
            #pragma unroll
            for (int h = 0; h < 2; h++) {
                const long row = bm + wm + tm * 16 + (l >> 2) + h * 8;
                float v0 = acc[tm][nf][2*h]     + bb0;
                float v1 = acc[tm][nf][2*h + 1] + bb1;
                if (EPI == 4) { v0 = gelu_exact(v0); v1 = gelu_exact(v1); }
                const long idx = row * (long)ldc + col;
                if (EPI == 2) {
                    float2 t = *(float2*)(Cf + idx);
                    t.x += v0; t.y += v1;
                    *(float2*)(Cf + idx) = t;
                } else {
                    __nv_bfloat16 h0 = __float2bfloat16(v0);
                    __nv_bfloat16 h1 = __float2bfloat16(v1);
                    __nv_bfloat162 hv; hv.x = h0; hv.y = h1;
                    *(__nv_bfloat162*)(Cb + idx) = hv;
                    __nv_bfloat162 lv;
                    lv.x = __float2bfloat16(v0 - __bfloat162float(h0));
                    lv.y = __float2bfloat16(v1 - __bfloat162float(h1));
                    *(__nv_bfloat162*)(Cb + idx + planeC) = lv;
                }
            }
        }
    }
}

// =================== Fused flash attention =================================
// grid (N_/128, B_*H_). 8 warps; warp = 16 queries. Streams K/V^T in 64-key
// chunks (3-stage cp.async). Online softmax in fp32 regs, split-bf16 P@V.
// x += attn_out (residual fused).
__global__ void __launch_bounds__(256)
flash_attn(const __nv_bfloat16* __restrict__ qkv, const __nv_bfloat16* __restrict__ vt,
           float* __restrict__ x, long planeQ, long planeV)
{
    extern __shared__ char sm[];
    const uint32_t smb = (smem_u32(sm) + 127) & ~127u;
    const uint32_t Qb = smb;             // 2 planes x 16384
    const uint32_t St = smb + 32768;     // 3 stages x 32768 (Khi,Klo,Vhi,Vlo)

    const int tid = threadIdx.x, wid = tid >> 5, l = tid & 31;
    const int qt = blockIdx.x, z = blockIdx.y;
    const int b = z / H_, h = z % H_;
    const long tokq = (long)b * N_ + qt * 128;

    // Q tile loads (committed together with chunk 0)
    #pragma unroll
    for (int p = 0; p < 2; p++)
        #pragma unroll
        for (int j = 0; j < 4; j++) {
            int idx = tid * 4 + j;
            int row = idx >> 3, c16 = idx & 7;
            cpa16(Qb + p*16384 + swz(row*128 + c16*16),
                  qkv + p*planeQ + (tokq + row)*QKVN + h*HD_ + c16*8);
        }

    auto load_kv = [&](int c, int st) {
        const uint32_t base = St + st * 32768;
        #pragma unroll
        for (int p = 0; p < 2; p++)
            #pragma unroll
            for (int j = 0; j < 2; j++) {
                int idx = tid * 2 + j;
                int row = idx >> 3, c16 = idx & 7;
                cpa16(base + p*8192 + swz(row*128 + c16*16),
                      qkv + p*planeQ + ((long)b*N_ + c*64 + row)*QKVN + D_ + h*HD_ + c16*8);
                cpa16(base + 16384 + p*8192 + swz(row*128 + c16*16),
                      vt + p*planeV + (long)z*HD_*N_ + (long)row*N_ + c*64 + c16*8);
            }
        CP_COMMIT();
    };

    load_kv(0, 0);
    load_kv(1, 1);

    float o[8][4];
    #pragma unroll
    for (int i = 0; i < 8; i++)
        #pragma unroll
        for (int q = 0; q < 4; q++) o[i][q] = 0.f;
    float m0 = -1e30f, m1 = -1e30f, rs0 = 0.f, rs1 = 0.f;

    const int NCH = N_ / 64;   // 8
    for (int c = 0; c < NCH; c++) {
        if (c < NCH - 1) asm volatile("cp.async.wait_group 1;" ::: "memory");
        else             asm volatile("cp.async.wait_group 0;" ::: "memory");
        __syncthreads();
        if (c + 2 < NCH) load_kv(c + 2, (c + 2) % 3);

        const uint32_t Kst = St + (c % 3) * 32768;
        const uint32_t Vst = Kst + 16384;

        // ---- S = (Q @ K^T) * 0.125, split 3-pass ----
        float s[8][4];
        #pragma unroll
        for (int i = 0; i < 8; i++)
            #pragma unroll
            for (int q = 0; q < 4; q++) s[i][q] = 0.f;

        #pragma unroll
        for (int kk = 0; kk < 4; kk++) {
            uint32_t ah[4], al[4];
            {
                int row = wid * 16 + (l & 15);
                uint32_t off = row * 128 + kk * 32 + ((l >> 4) * 16);
                ldsm4(ah, Qb + swz(off));
                ldsm4(al, Qb + 16384 + swz(off));
            }
            #pragma unroll
            for (int nb = 0; nb < 4; nb++) {
                int rowB = nb * 16 + (l & 7) + ((l >> 4) << 3);
                uint32_t off = rowB * 128 + kk * 32 + (((l >> 3) & 1) * 16);
                uint32_t bh[4], bl[4];
                ldsm4(bh, Kst + swz(off));
                ldsm4(bl, Kst + 8192 + swz(off));
                mma16816(s[2*nb],   ah, bh); mma16816(s[2*nb+1], ah, bh + 2);
                mma16816(s[2*nb],   ah, bl); mma16816(s[2*nb+1], ah, bl + 2);
                mma16816(s[2*nb],   al, bh); mma16816(s[2*nb+1], al, bh + 2);
            }
        }
        #pragma unroll
        for (int i = 0; i < 8; i++)
            #pragma unroll
            for (int q = 0; q < 4; q++) s[i][q] *= 0.125f;

        // ---- online softmax ----
        float mx0 = -1e30f, mx1 = -1e30f;
        #pragma unroll
        for (int i = 0; i < 8; i++) {
            mx0 = fmaxf(mx0, fmaxf(s[i][0], s[i][1]));
            mx1 = fmaxf(mx1, fmaxf(s[i][2], s[i][3]));
        }
        mx0 = fmaxf(mx0, __shfl_xor_sync(0xFFFFFFFFu, mx0, 1));
        mx0 = fmaxf(mx0, __shfl_xor_sync(0xFFFFFFFFu, mx0, 2));
        mx1 = fmaxf(mx1, __shfl_xor_sync(0xFFFFFFFFu, mx1, 1));
        mx1 = fmaxf(mx1, __shfl_xor_sync(0xFFFFFFFFu, mx1, 2));
        float nm0 = fmaxf(m0, mx0), nm1 = fmaxf(m1, mx1);
        float sc0 = __expf(m0 - nm0), sc1 = __expf(m1 - nm1);
        m0 = nm0; m1 = nm1;

        float sum0 = 0.f, sum1 = 0.f;
        #pragma unroll
        for (int i = 0; i < 8; i++) {
            s[i][0] = __expf(s[i][0] - m0);
            s[i][1] = __expf(s[i][1] - m0);
            s[i][2] = __expf(s[i][2] - m1);
            s[i][3] = __expf(s[i][3] - m1);
            sum0 += s[i][0] + s[i][1];
            sum1 += s[i][2] + s[i][3];
        }
        sum0 += __shfl_xor_sync(0xFFFFFFFFu, sum0, 1);
        sum0 += __shfl_xor_sync(0xFFFFFFFFu, sum0, 2);
        sum1 += __shfl_xor_sync(0xFFFFFFFFu, sum1, 1);
        sum1 += __shfl_xor_sync(0xFFFFFFFFu, sum1, 2);
        rs0 = rs0 * sc0 + sum0;
        rs1 = rs1 * sc1 + sum1;

        #pragma unroll
        for (int i = 0; i < 8; i++) {
            o[i][0] *= sc0; o[i][1] *= sc0;
            o[i][2] *= sc1; o[i][3] *= sc1;
        }

        // ---- O += P @ V, split 3-pass (P from registers) ----
        #pragma unroll
        for (int kc = 0; kc < 4; kc++) {
            uint32_t ah[4], al[4];
            ah[0] = pkh(s[2*kc][0],   s[2*kc][1]);
            ah[1] = pkh(s[2*kc][2],   s[2*kc][3]);
            ah[2] = pkh(s[2*kc+1][0], s[2*kc+1][1]);
            ah[3] = pkh(s[2*kc+1][2], s[2*kc+1][3]);
            al[0] = pkl(s[2*kc][0],   s[2*kc][1]);
            al[1] = pkl(s[2*kc][2],   s[2*kc][3]);
            al[2] = pkl(s[2*kc+1][0], s[2*kc+1][1]);
            al[3] = pkl(s[2*kc+1][2], s[2*kc+1][3]);
            #pragma unroll
            for (int nb = 0; nb < 4; nb++) {
                int rowB = nb * 16 + (l & 7) + ((l >> 4) << 3);
                uint32_t off = rowB * 128 + kc * 32 + (((l >> 3) & 1) * 16);
                uint32_t bh[4], bl[4];
                ldsm4(bh, Vst + swz(off));
                ldsm4(bl, Vst + 8192 + swz(off));
                mma16816(o[2*nb],   ah, bh); mma16816(o[2*nb+1], ah, bh + 2);
                mma16816(o[2*nb],   ah, bl); mma16816(o[2*nb+1], ah, bl + 2);
                mma16816(o[2*nb],   al, bh); mma16816(o[2*nb+1], al, bh + 2);
            }
        }
    }

    // ---- epilogue: x += O / rowsum ----
    const float inv0 = 1.f / rs0, inv1 = 1.f / rs1;
    const long tok0 = tokq + wid * 16 + (l >> 2);
    const long col = h * HD_ + (l & 3) * 2;
    #pragma unroll
    for (int nf = 0; nf < 8; nf++) {
        float2* p0 = (float2*)(x + tok0 * D_ + col + nf * 8);
        float2 t0 = *p0;
        t0.x += o[nf][0] * inv0; t0.y += o[nf][1] * inv0;
        *p0 = t0;
        float2* p1 = (float2*)(x + (tok0 + 8) * D_ + col + nf * 8);
        float2 t1 = *p1;
        t1.x += o[nf][2] * inv1; t1.y += o[nf][3] * inv1;
        *p1 = t1;
    }
}

// =================== driver ================================================
extern "C" void kernel_launch(void* const* d_in, const int* in_sizes, int n_in,
                              void* d_out, int out_size)
{
    const float* x0  = (const float*)d_in[0];
    const float* Wq  = (const float*)d_in[1];
    const float* bq  = (const float*)d_in[2];
    const float* Wk  = (const float*)d_in[3];
    const float* bk  = (const float*)d_in[4];
    const float* Wv  = (const float*)d_in[5];
    const float* bv  = (const float*)d_in[6];
    const float* g1  = (const float*)d_in[7];
    const float* be1 = (const float*)d_in[8];
    const float* g2  = (const float*)d_in[9];
    const float* be2 = (const float*)d_in[10];
    const float* W0  = (const float*)d_in[11];
    const float* b0  = (const float*)d_in[12];
    const float* W1  = (const float*)d_in[13];
    const float* b1  = (const float*)d_in[14];

    float* x = (float*)d_out;

    __nv_bfloat16 *lns, *qkvs, *vts, *ffs, *wqkv, *w0t, *w1t;
    float* bqkv;
    cudaGetSymbolAddress((void**)&lns,  g_lns);
    cudaGetSymbolAddress((void**)&qkvs, g_qkvs);
    cudaGetSymbolAddress((void**)&vts,  g_vts);
    cudaGetSymbolAddress((void**)&ffs,  g_ffs);
    cudaGetSymbolAddress((void**)&wqkv, g_wqkv);
    cudaGetSymbolAddress((void**)&w0t,  g_w0t);
    cudaGetSymbolAddress((void**)&w1t,  g_w1t);
    cudaGetSymbolAddress((void**)&bqkv, g_bqkv);

    const int SMG = 3 * (128*128 + 128*128) + 256;   // 98560
    const int SMF = 32768 + 3 * 32768 + 256;          // 131328
    cudaFuncSetAttribute(gemm_mma<2>, cudaFuncAttributeMaxDynamicSharedMemorySize, SMG);
    cudaFuncSetAttribute(gemm_mma<3>, cudaFuncAttributeMaxDynamicSharedMemorySize, SMG);
    cudaFuncSetAttribute(gemm_mma<4>, cudaFuncAttributeMaxDynamicSharedMemorySize, SMG);
    cudaFuncSetAttribute(flash_attn,  cudaFuncAttributeMaxDynamicSharedMemorySize, SMF);

    cudaMemcpyAsync(x, x0, sizeof(float)*M_*D_, cudaMemcpyDeviceToDevice);

    // ---- weight preprocessing (once per launch) ----
    dim3 tb(32, 8);
    const long WQKV = (long)QKVN * D_;
    tsplit_kernel<<<dim3(D_/32, D_/32), tb>>>(Wq, wqkv,             D_, D_, WQKV);
    tsplit_kernel<<<dim3(D_/32, D_/32), tb>>>(Wk, wqkv + (long)D_*D_,   D_, D_, WQKV);
    tsplit_kernel<<<dim3(D_/32, D_/32), tb>>>(Wv, wqkv + (long)2*D_*D_, D_, D_, WQKV);
    tsplit_kernel<<<dim3(F_/32, D_/32), tb>>>(W0, w0t, F_, D_, (long)D_*F_);
    tsplit_kernel<<<dim3(D_/32, F_/32), tb>>>(W1, w1t, D_, F_, (long)D_*F_);
    cat_bias<<<9, 256>>>(bq, bk, bv, bqkv);

    const long MD   = (long)M_ * D_;
    const long MQ   = (long)M_ * QKVN;
    const long MF   = (long)M_ * F_;
    const long WDF  = (long)D_ * F_;
    const long VTP  = (long)B_ * H_ * HD_ * N_;

    for (int blk = 0; blk < NBLOCKS; blk++) {
        // ---- attention ----
        ln_kernel<<<M_, 256>>>(x, g1, be1, lns, MD);

        gemm_mma<3><<<dim3(QKVN/128, M_/128), 256, SMG>>>(
            lns, wqkv, bqkv, qkvs, D_, D_, D_, QKVN, MD, WQKV, MQ);

        vtrans<<<dim3(HD_/32, N_/32, B_*H_), tb>>>(qkvs, vts, MQ, VTP);

        flash_attn<<<dim3(N_/128, B_*H_), 256, SMF>>>(qkvs, vts, x, MQ, VTP);

        // ---- MLP ----
        ln_kernel<<<M_, 256>>>(x, g2, be2, lns, MD);

        gemm_mma<4><<<dim3(F_/128, M_/128), 256, SMG>>>(
            lns, w0t, b0, ffs, D_, D_, D_, F_, MD, WDF, MF);

        gemm_mma<2><<<dim3(D_/128, M_/128), 256, SMG>>>(
            ffs, w1t, b1, x, F_, F_, F_, D_, MF, WDF, 0);
    }
    (void)in_sizes; (void)n_in; (void)out_size;
}

// round 5
// speedup vs baseline: 3.8123x; 1.1417x over previous
#include <cuda_runtime.h>
#include <cuda_bf16.h>
#include <math.h>
#include <stdint.h>

// Problem constants
#define B_  4
#define N_  512
#define D_  768
#define F_  3072
#define H_  12
#define HD_ 64
#define M_  (B_*N_)   // 2048 tokens
#define NBLOCKS 12
#define QKVN (3*D_)   // 2304

// =================== scratch (static device globals) ========================
// split-bf16 planes: [hi plane][lo plane], plane offset = element count
__device__ __align__(256) __nv_bfloat16 g_lns [2L*M_*D_];
__device__ __align__(256) __nv_bfloat16 g_qkvs[2L*M_*QKVN];
__device__ __align__(256) __nv_bfloat16 g_ffs [2L*M_*F_];
__device__ __align__(256) __nv_bfloat16 g_wqkv[2L*QKVN*D_];
__device__ __align__(256) __nv_bfloat16 g_w0t [2L*D_*F_];
__device__ __align__(256) __nv_bfloat16 g_w1t [2L*D_*F_];
__device__ float g_bqkv[QKVN];

// =================== PTX helpers ===========================================
__device__ __forceinline__ uint32_t smem_u32(const void* p){
    uint32_t a;
    asm("{ .reg .u64 t; cvta.to.shared.u64 t, %1; cvt.u32.u64 %0, t; }" : "=r"(a) : "l"(p));
    return a;
}
__device__ __forceinline__ void cpa16(uint32_t d, const void* s){
    asm volatile("cp.async.cg.shared.global [%0], [%1], 16;" :: "r"(d), "l"(s));
}
#define CP_COMMIT() asm volatile("cp.async.commit_group;" ::: "memory")

__device__ __forceinline__ void ldsm4(uint32_t* r, uint32_t addr){
    asm volatile("ldmatrix.sync.aligned.m8n8.x4.shared.b16 {%0,%1,%2,%3}, [%4];"
                 : "=r"(r[0]), "=r"(r[1]), "=r"(r[2]), "=r"(r[3]) : "r"(addr));
}
__device__ __forceinline__ void ldsm4t(uint32_t* r, uint32_t addr){
    asm volatile("ldmatrix.sync.aligned.m8n8.x4.trans.shared.b16 {%0,%1,%2,%3}, [%4];"
                 : "=r"(r[0]), "=r"(r[1]), "=r"(r[2]), "=r"(r[3]) : "r"(addr));
}
__device__ __forceinline__ void mma16816(float* c, const uint32_t* a, const uint32_t* b){
    asm volatile(
        "mma.sync.aligned.m16n8k16.row.col.f32.bf16.bf16.f32 "
        "{%0,%1,%2,%3}, {%4,%5,%6,%7}, {%8,%9}, {%0,%1,%2,%3};"
        : "+f"(c[0]), "+f"(c[1]), "+f"(c[2]), "+f"(c[3])
        : "r"(a[0]), "r"(a[1]), "r"(a[2]), "r"(a[3]), "r"(b[0]), "r"(b[1]));
}
__device__ __forceinline__ float gelu_exact(float v){
    return 0.5f * v * (1.0f + erff(v * 0.70710678118654752f));
}
__device__ __forceinline__ uint32_t swz(uint32_t off){ return off ^ ((off >> 3) & 0x70); }
__device__ __forceinline__ uint32_t pkh(float x, float y){
    __nv_bfloat162 h; h.x = __float2bfloat16(x); h.y = __float2bfloat16(y);
    return *(uint32_t*)&h;
}
__device__ __forceinline__ uint32_t pkl(float x, float y){
    float rx = x - __bfloat162float(__float2bfloat16(x));
    float ry = y - __bfloat162float(__float2bfloat16(y));
    __nv_bfloat162 h; h.x = __float2bfloat16(rx); h.y = __float2bfloat16(ry);
    return *(uint32_t*)&h;
}

// =================== LayerNorm: warp per row, shuffle reductions ============
__global__ void __launch_bounds__(256)
ln_kernel(const float* __restrict__ x,
          const float* __restrict__ g,
          const float* __restrict__ be,
          __nv_bfloat16* __restrict__ out, long plane)
{
    const int w = threadIdx.x >> 5, l = threadIdx.x & 31;
    const long row = (long)blockIdx.x * 8 + w;
    const float* xr = x + row * D_;

    float4 v[6];
    float s = 0.f;
    #pragma unroll
    for (int i = 0; i < 6; i++) {
        v[i] = *(const float4*)(xr + i * 128 + l * 4);
        s += v[i].x + v[i].y + v[i].z + v[i].w;
    }
    #pragma unroll
    for (int o = 16; o > 0; o >>= 1) s += __shfl_xor_sync(0xFFFFFFFFu, s, o);
    const float mu = s * (1.0f / D_);

    float vs = 0.f;
    #pragma unroll
    for (int i = 0; i < 6; i++) {
        float a = v[i].x - mu, b2 = v[i].y - mu, c = v[i].z - mu, d = v[i].w - mu;
        vs += a*a + b2*b2 + c*c + d*d;
    }
    #pragma unroll
    for (int o = 16; o > 0; o >>= 1) vs += __shfl_xor_sync(0xFFFFFFFFu, vs, o);
    const float inv = rsqrtf(vs * (1.0f / D_) + 1e-5f);

    __nv_bfloat16* orow = out + row * D_;
    #pragma unroll
    for (int i = 0; i < 6; i++) {
        const int col = i * 128 + l * 4;
        float4 gg = *(const float4*)(g  + col);
        float4 bb = *(const float4*)(be + col);
        float y0 = (v[i].x - mu) * inv * gg.x + bb.x;
        float y1 = (v[i].y - mu) * inv * gg.y + bb.y;
        float y2 = (v[i].z - mu) * inv * gg.z + bb.z;
        float y3 = (v[i].w - mu) * inv * gg.w + bb.w;
        uint2 hp; hp.x = pkh(y0, y1); hp.y = pkh(y2, y3);
        *(uint2*)(orow + col) = hp;
        uint2 lp; lp.x = pkl(y0, y1); lp.y = pkl(y2, y3);
        *(uint2*)(orow + plane + col) = lp;
    }
}

// =================== Weight transpose + split (fp32 in) =====================
__global__ void tsplit_kernel(const float* __restrict__ in, __nv_bfloat16* __restrict__ out,
                              int ldin, int ldout, long plane)
{
    __shared__ float t[32][33];
    const int c0 = blockIdx.x * 32, r0 = blockIdx.y * 32;
    const int tx = threadIdx.x, ty = threadIdx.y;
    #pragma unroll
    for (int i = 0; i < 32; i += 8)
        t[ty+i][tx] = in[(long)(r0+ty+i) * ldin + c0 + tx];
    __syncthreads();
    #pragma unroll
    for (int i = 0; i < 32; i += 8) {
        float v = t[tx][ty+i];
        __nv_bfloat16 h = __float2bfloat16(v);
        long o = (long)(c0+ty+i) * ldout + r0 + tx;
        out[o] = h;
        out[o + plane] = __float2bfloat16(v - __bfloat162float(h));
    }
}

__global__ void cat_bias(const float* __restrict__ a, const float* __restrict__ k,
                         const float* __restrict__ v, float* __restrict__ o)
{
    int i = blockIdx.x * 256 + threadIdx.x;
    if (i < QKVN)
        o[i] = (i < D_) ? a[i] : (i < 2*D_) ? k[i - D_] : v[i - 2*D_];
}

// =================== HMMA GEMM, 3-stage pipeline, 2 CTAs/SM ================
// D[M,N] = epilogue(A @ B^T + bias). Split planes, 3 passes (hi.hi, hi.lo, lo.hi).
// CTA 128x128, BK=64, 8 warps 4x2, warp tile 32x64. Split-K over blockIdx.z.
// EPI 3: split-bf16 C = v + bias | EPI 4: split-bf16 C = gelu(v + bias)
// EPI 5: fp32 atomicAdd(C, v [+ bias if z==0])
template<int EPI>
__global__ void __launch_bounds__(256, 2)
gemm_mma(const __nv_bfloat16* __restrict__ A, const __nv_bfloat16* __restrict__ B,
         const float* __restrict__ bias, void* __restrict__ Cv,
         int K, int lda, int ldb, int ldc,
         long planeA, long planeB, long planeC)
{
    extern __shared__ char sm[];
    constexpr int ABYTES = 128 * 128;
    constexpr int BBYTES = 128 * 128;
    constexpr int STG = ABYTES + BBYTES;

    const uint32_t smb = (smem_u32(sm) + 127) & ~127u;

    const int tid = threadIdx.x;
    const int wid = tid >> 5, l = tid & 31;
    const int wm = (wid & 3) * 32;
    const int wn = (wid >> 2) * 64;

    const long bm = (long)blockIdx.y * 128;
    const long bn = (long)blockIdx.x * 128;
    const long koff = (long)blockIdx.z * K;

    float* Cf = (float*)Cv;
    __nv_bfloat16* Cb = (__nv_bfloat16*)Cv;

    const int kch = K / 64;
    const int NC = 3 * kch;

    float acc[2][8][4];
    #pragma unroll
    for (int i = 0; i < 2; i++)
        #pragma unroll
        for (int j = 0; j < 8; j++)
            #pragma unroll
            for (int q = 0; q < 4; q++) acc[i][j][q] = 0.f;

    auto load_chunk = [&](int c, int st) {
        const int p  = c / kch;
        const long kk = koff + (long)(c - p * kch) * 64;
        const __nv_bfloat16* Ap = A + ((p == 2) ? planeA : 0) + kk;
        const __nv_bfloat16* Bp = B + ((p == 1) ? planeB : 0) + kk;
        const uint32_t sA = smb + st * STG;
        const uint32_t sB = sA + ABYTES;
        #pragma unroll
        for (int j = 0; j < 4; j++) {
            int idx = tid * 4 + j;
            int row = idx >> 3, c16 = (idx & 7) * 16;
            cpa16(sA + swz(row * 128 + c16),
                  (const char*)(Ap + (bm + row) * lda) + c16);
        }
        #pragma unroll
        for (int j = 0; j < 4; j++) {
            int idx = tid * 4 + j;
            int row = idx >> 3, c16 = (idx & 7) * 16;
            cpa16(sB + swz(row * 128 + c16),
                  (const char*)(Bp + (bn + row) * ldb) + c16);
        }
        CP_COMMIT();
    };

    auto compute = [&](int st) {
        const uint32_t bA = smb + st * STG;
        const uint32_t bB = bA + ABYTES;
        #pragma unroll
        for (int kk2 = 0; kk2 < 4; kk2++) {
            uint32_t a[2][4];
            #pragma unroll
            for (int tm = 0; tm < 2; tm++) {
                int row = wm + tm * 16 + (l & 15);
                uint32_t off = row * 128 + kk2 * 32 + ((l >> 4) * 16);
                ldsm4(a[tm], bA + swz(off));
            }
            #pragma unroll
            for (int nb = 0; nb < 4; nb++) {
                uint32_t b[4];
                int rowB = wn + nb * 16 + (l & 7) + ((l >> 4) << 3);
                uint32_t off = rowB * 128 + kk2 * 32 + (((l >> 3) & 1) * 16);
                ldsm4(b, bB + swz(off));
                #pragma unroll
                for (int tm = 0; tm < 2; tm++) {
                    mma16816(acc[tm][2*nb],   a[tm], b);
                    mma16816(acc[tm][2*nb+1], a[tm], b + 2);
                }
            }
        }
    };

    load_chunk(0, 0);
    load_chunk(1, 1);
    for (int c = 0; c < NC; c++) {
        if (c < NC - 1) asm volatile("cp.async.wait_group 1;" ::: "memory");
        else            asm volatile("cp.async.wait_group 0;" ::: "memory");
        __syncthreads();
        if (c + 2 < NC) load_chunk(c + 2, (c + 2) % 3);
        compute(c % 3);
    }

    // -------- epilogue --------
    const bool addb = (EPI != 5) || (blockIdx.z == 0);
    #pragma unroll
    for (int tm = 0; tm < 2; tm++) {
        #pragma unroll
        for (int nf = 0; nf < 8; nf++) {
            const long col = bn + wn + nf * 8 + (l & 3) * 2;
            const float bb0 = (bias && addb) ? bias[col]     : 0.f;
            const float bb1 = (bias && addb) ? bias[col + 1] : 0.f;
            #pragma unroll
            for (int h = 0; h < 2; h++) {
                const long row = bm + wm + tm * 16 + (l >> 2) + h * 8;
                float v0 = acc[tm][nf][2*h]     + bb0;
                float v1 = acc[tm][nf][2*h + 1] + bb1;
                if (EPI == 4) { v0 = gelu_exact(v0); v1 = gelu_exact(v1); }
                const long idx = row * (long)ldc + col;
                if (EPI == 5) {
                    atomicAdd(Cf + idx, v0);
                    atomicAdd(Cf + idx + 1, v1);
                } else {
                    __nv_bfloat16 h0 = __float2bfloat16(v0);
                    __nv_bfloat16 h1 = __float2bfloat16(v1);
                    __nv_bfloat162 hv; hv.x = h0; hv.y = h1;
                    *(__nv_bfloat162*)(Cb + idx) = hv;
                    __nv_bfloat162 lv;
                    lv.x = __float2bfloat16(v0 - __bfloat162float(h0));
                    lv.y = __float2bfloat16(v1 - __bfloat162float(h1));
                    *(__nv_bfloat162*)(Cb + idx + planeC) = lv;
                }
            }
        }
    }
}

// =================== Fused flash attention =================================
// grid (N_/128, B_*H_). 8 warps x 16 queries. K and V both streamed straight
// from the qkv buffer in 64-key chunks (2-stage cp.async, 2 CTAs/SM).
// V consumed via ldmatrix.trans (no pre-transpose). Online softmax, split-bf16
// P@V, residual x += out fused.
__global__ void __launch_bounds__(256, 2)
flash_attn(const __nv_bfloat16* __restrict__ qkv, float* __restrict__ x, long planeQ)
{
    extern __shared__ char sm[];
    const uint32_t smb = (smem_u32(sm) + 127) & ~127u;
    const uint32_t Qb = smb;             // Q: hi 16K + lo 16K
    const uint32_t St = smb + 32768;     // 2 stages x 32K (Khi 8K, Klo 8K, Vhi 8K, Vlo 8K)

    const int tid = threadIdx.x, wid = tid >> 5, l = tid & 31;
    const int qt = blockIdx.x, z = blockIdx.y;
    const int b = z / H_, h = z % H_;
    const long tokq = (long)b * N_ + qt * 128;

    // Q tile loads (committed with chunk 0)
    #pragma unroll
    for (int p = 0; p < 2; p++)
        #pragma unroll
        for (int j = 0; j < 4; j++) {
            int idx = tid * 4 + j;
            int row = idx >> 3, c16 = idx & 7;
            cpa16(Qb + p*16384 + swz(row*128 + c16*16),
                  qkv + p*planeQ + (tokq + row)*QKVN + h*HD_ + c16*8);
        }

    auto load_kv = [&](int c, int st) {
        const uint32_t base = St + st * 32768;
        #pragma unroll
        for (int p = 0; p < 2; p++)
            #pragma unroll
            for (int j = 0; j < 2; j++) {
                int idx = tid * 2 + j;
                int row = idx >> 3, c16 = idx & 7;
                const long tok = (long)b * N_ + c * 64 + row;
                cpa16(base + p*8192 + swz(row*128 + c16*16),
                      qkv + p*planeQ + tok*QKVN + D_ + h*HD_ + c16*8);
                cpa16(base + 16384 + p*8192 + swz(row*128 + c16*16),
                      qkv + p*planeQ + tok*QKVN + 2*D_ + h*HD_ + c16*8);
            }
        CP_COMMIT();
    };

    load_kv(0, 0);
    load_kv(1, 1);

    float o[8][4];
    #pragma unroll
    for (int i = 0; i < 8; i++)
        #pragma unroll
        for (int q = 0; q < 4; q++) o[i][q] = 0.f;
    float m0 = -1e30f, m1 = -1e30f, rs0 = 0.f, rs1 = 0.f;

    const int NCH = N_ / 64;   // 8
    for (int c = 0; c < NCH; c++) {
        if (c < NCH - 1) asm volatile("cp.async.wait_group 1;" ::: "memory");
        else             asm volatile("cp.async.wait_group 0;" ::: "memory");
        __syncthreads();

        const uint32_t Kst = St + (c & 1) * 32768;
        const uint32_t Vst = Kst + 16384;

        // ---- S = (Q @ K^T) * 0.125, split 3-pass ----
        float s[8][4];
        #pragma unroll
        for (int i = 0; i < 8; i++)
            #pragma unroll
            for (int q = 0; q < 4; q++) s[i][q] = 0.f;

        #pragma unroll
        for (int kk = 0; kk < 4; kk++) {
            uint32_t ah[4], al[4];
            {
                int row = wid * 16 + (l & 15);
                uint32_t off = row * 128 + kk * 32 + ((l >> 4) * 16);
                ldsm4(ah, Qb + swz(off));
                ldsm4(al, Qb + 16384 + swz(off));
            }
            #pragma unroll
            for (int nb = 0; nb < 4; nb++) {
                int rowB = nb * 16 + (l & 7) + ((l >> 4) << 3);
                uint32_t off = rowB * 128 + kk * 32 + (((l >> 3) & 1) * 16);
                uint32_t bh[4], bl[4];
                ldsm4(bh, Kst + swz(off));
                ldsm4(bl, Kst + 8192 + swz(off));
                mma16816(s[2*nb],   ah, bh); mma16816(s[2*nb+1], ah, bh + 2);
                mma16816(s[2*nb],   ah, bl); mma16816(s[2*nb+1], ah, bl + 2);
                mma16816(s[2*nb],   al, bh); mma16816(s[2*nb+1], al, bh + 2);
            }
        }
        #pragma unroll
        for (int i = 0; i < 8; i++)
            #pragma unroll
            for (int q = 0; q < 4; q++) s[i][q] *= 0.125f;

        // ---- online softmax ----
        float mx0 = -1e30f, mx1 = -1e30f;
        #pragma unroll
        for (int i = 0; i < 8; i++) {
            mx0 = fmaxf(mx0, fmaxf(s[i][0], s[i][1]));
            mx1 = fmaxf(mx1, fmaxf(s[i][2], s[i][3]));
        }
        mx0 = fmaxf(mx0, __shfl_xor_sync(0xFFFFFFFFu, mx0, 1));
        mx0 = fmaxf(mx0, __shfl_xor_sync(0xFFFFFFFFu, mx0, 2));
        mx1 = fmaxf(mx1, __shfl_xor_sync(0xFFFFFFFFu, mx1, 1));
        mx1 = fmaxf(mx1, __shfl_xor_sync(0xFFFFFFFFu, mx1, 2));
        float nm0 = fmaxf(m0, mx0), nm1 = fmaxf(m1, mx1);
        float sc0 = __expf(m0 - nm0), sc1 = __expf(m1 - nm1);
        m0 = nm0; m1 = nm1;

        float sum0 = 0.f, sum1 = 0.f;
        #pragma unroll
        for (int i = 0; i < 8; i++) {
            s[i][0] = __expf(s[i][0] - m0);
            s[i][1] = __expf(s[i][1] - m0);
            s[i][2] = __expf(s[i][2] - m1);
            s[i][3] = __expf(s[i][3] - m1);
            sum0 += s[i][0] + s[i][1];
            sum1 += s[i][2] + s[i][3];
        }
        sum0 += __shfl_xor_sync(0xFFFFFFFFu, sum0, 1);
        sum0 += __shfl_xor_sync(0xFFFFFFFFu, sum0, 2);
        sum1 += __shfl_xor_sync(0xFFFFFFFFu, sum1, 1);
        sum1 += __shfl_xor_sync(0xFFFFFFFFu, sum1, 2);
        rs0 = rs0 * sc0 + sum0;
        rs1 = rs1 * sc1 + sum1;

        #pragma unroll
        for (int i = 0; i < 8; i++) {
            o[i][0] *= sc0; o[i][1] *= sc0;
            o[i][2] *= sc1; o[i][3] *= sc1;
        }

        // ---- O += P @ V (V via ldmatrix.trans), split 3-pass ----
        #pragma unroll
        for (int kc = 0; kc < 4; kc++) {
            uint32_t ah[4], al[4];
            ah[0] = pkh(s[2*kc][0],   s[2*kc][1]);
            ah[1] = pkh(s[2*kc][2],   s[2*kc][3]);
            ah[2] = pkh(s[2*kc+1][0], s[2*kc+1][1]);
            ah[3] = pkh(s[2*kc+1][2], s[2*kc+1][3]);
            al[0] = pkl(s[2*kc][0],   s[2*kc][1]);
            al[1] = pkl(s[2*kc][2],   s[2*kc][3]);
            al[2] = pkl(s[2*kc+1][0], s[2*kc+1][1]);
            al[3] = pkl(s[2*kc+1][2], s[2*kc+1][3]);
            #pragma unroll
            for (int nb = 0; nb < 4; nb++) {
                // V stored [64 keys x 64 hd]; trans-ldsm: rows = keys
                uint32_t off = (kc*16 + (l & 15)) * 128 + nb*32 + ((l >> 4) * 16);
                uint32_t bh[4], bl[4];
                ldsm4t(bh, Vst + swz(off));
                ldsm4t(bl, Vst + 8192 + swz(off));
                mma16816(o[2*nb],   ah, bh); mma16816(o[2*nb+1], ah, bh + 2);
                mma16816(o[2*nb],   ah, bl); mma16816(o[2*nb+1], ah, bl + 2);
                mma16816(o[2*nb],   al, bh); mma16816(o[2*nb+1], al, bh + 2);
            }
        }

        __syncthreads();                        // all warps done with stage c&1
        if (c + 2 < NCH) load_kv(c + 2, c & 1);
    }

    // ---- epilogue: x += O / rowsum ----
    const float inv0 = 1.f / rs0, inv1 = 1.f / rs1;
    const long tok0 = tokq + wid * 16 + (l >> 2);
    const long col = h * HD_ + (l & 3) * 2;
    #pragma unroll
    for (int nf = 0; nf < 8; nf++) {
        float2* p0 = (float2*)(x + tok0 * D_ + col + nf * 8);
        float2 t0 = *p0;
        t0.x += o[nf][0] * inv0; t0.y += o[nf][1] * inv0;
        *p0 = t0;
        float2* p1 = (float2*)(x + (tok0 + 8) * D_ + col + nf * 8);
        float2 t1 = *p1;
        t1.x += o[nf][2] * inv1; t1.y += o[nf][3] * inv1;
        *p1 = t1;
    }
}

// =================== driver ================================================
extern "C" void kernel_launch(void* const* d_in, const int* in_sizes, int n_in,
                              void* d_out, int out_size)
{
    const float* x0  = (const float*)d_in[0];
    const float* Wq  = (const float*)d_in[1];
    const float* bq  = (const float*)d_in[2];
    const float* Wk  = (const float*)d_in[3];
    const float* bk  = (const float*)d_in[4];
    const float* Wv  = (const float*)d_in[5];
    const float* bv  = (const float*)d_in[6];
    const float* g1  = (const float*)d_in[7];
    const float* be1 = (const float*)d_in[8];
    const float* g2  = (const float*)d_in[9];
    const float* be2 = (const float*)d_in[10];
    const float* W0  = (const float*)d_in[11];
    const float* b0  = (const float*)d_in[12];
    const float* W1  = (const float*)d_in[13];
    const float* b1  = (const float*)d_in[14];

    float* x = (float*)d_out;

    __nv_bfloat16 *lns, *qkvs, *ffs, *wqkv, *w0t, *w1t;
    float* bqkv;
    cudaGetSymbolAddress((void**)&lns,  g_lns);
    cudaGetSymbolAddress((void**)&qkvs, g_qkvs);
    cudaGetSymbolAddress((void**)&ffs,  g_ffs);
    cudaGetSymbolAddress((void**)&wqkv, g_wqkv);
    cudaGetSymbolAddress((void**)&w0t,  g_w0t);
    cudaGetSymbolAddress((void**)&w1t,  g_w1t);
    cudaGetSymbolAddress((void**)&bqkv, g_bqkv);

    const int SMG = 3 * (128*128 + 128*128) + 256;   // 98560
    const int SMF = 32768 + 2 * 32768 + 256;          // 98560
    cudaFuncSetAttribute(gemm_mma<3>, cudaFuncAttributeMaxDynamicSharedMemorySize, SMG);
    cudaFuncSetAttribute(gemm_mma<4>, cudaFuncAttributeMaxDynamicSharedMemorySize, SMG);
    cudaFuncSetAttribute(gemm_mma<5>, cudaFuncAttributeMaxDynamicSharedMemorySize, SMG);
    cudaFuncSetAttribute(flash_attn,  cudaFuncAttributeMaxDynamicSharedMemorySize, SMF);

    cudaMemcpyAsync(x, x0, sizeof(float)*M_*D_, cudaMemcpyDeviceToDevice);

    // ---- weight preprocessing (once per launch) ----
    dim3 tb(32, 8);
    const long WQKV = (long)QKVN * D_;
    tsplit_kernel<<<dim3(D_/32, D_/32), tb>>>(Wq, wqkv,                 D_, D_, WQKV);
    tsplit_kernel<<<dim3(D_/32, D_/32), tb>>>(Wk, wqkv + (long)D_*D_,   D_, D_, WQKV);
    tsplit_kernel<<<dim3(D_/32, D_/32), tb>>>(Wv, wqkv + (long)2*D_*D_, D_, D_, WQKV);
    tsplit_kernel<<<dim3(F_/32, D_/32), tb>>>(W0, w0t, F_, D_, (long)D_*F_);
    tsplit_kernel<<<dim3(D_/32, F_/32), tb>>>(W1, w1t, D_, F_, (long)D_*F_);
    cat_bias<<<9, 256>>>(bq, bk, bv, bqkv);

    const long MD   = (long)M_ * D_;
    const long MQ   = (long)M_ * QKVN;
    const long MF   = (long)M_ * F_;
    const long WDF  = (long)D_ * F_;

    for (int blk = 0; blk < NBLOCKS; blk++) {
        // ---- attention ----
        ln_kernel<<<M_/8, 256>>>(x, g1, be1, lns, MD);

        gemm_mma<3><<<dim3(QKVN/128, M_/128), 256, SMG>>>(
            lns, wqkv, bqkv, qkvs, D_, D_, D_, QKVN, MD, WQKV, MQ);

        flash_attn<<<dim3(N_/128, B_*H_), 256, SMF>>>(qkvs, x, MQ);

        // ---- MLP ----
        ln_kernel<<<M_/8, 256>>>(x, g2, be2, lns, MD);

        gemm_mma<4><<<dim3(F_/128, M_/128), 256, SMG>>>(
            lns, w0t, b0, ffs, D_, D_, D_, F_, MD, WDF, MF);

        // MLP2: split-K x2, atomic residual accumulate into x
        gemm_mma<5><<<dim3(D_/128, M_/128, 2), 256, SMG>>>(
            ffs, w1t, b1, x, F_/2, F_, F_, D_, MF, WDF, 0);
    }
    (void)in_sizes; (void)n_in; (void)out_size;
}

// round 7
// speedup vs baseline: 4.2336x; 1.1105x over previous
#include <cuda_runtime.h>
#include <cuda_bf16.h>
#include <math.h>
#include <stdint.h>

// Problem constants
#define B_  4
#define N_  512
#define D_  768
#define F_  3072
#define H_  12
#define HD_ 64
#define M_  (B_*N_)   // 2048 tokens
#define NBLOCKS 12
#define QKVN (3*D_)   // 2304

// =================== scratch (static device globals) ========================
// split-bf16 planes: [hi plane][lo plane], plane offset = element count
__device__ __align__(256) __nv_bfloat16 g_lns [2L*M_*D_];
__device__ __align__(256) __nv_bfloat16 g_qkvs[2L*M_*QKVN];
__device__ __align__(256) __nv_bfloat16 g_ffs [2L*M_*F_];
__device__ __align__(256) float         g_ffw [2L*M_*F_];   // split-K fp32 partials
__device__ __align__(256) __nv_bfloat16 g_wqkv[2L*QKVN*D_];
__device__ __align__(256) __nv_bfloat16 g_w0t [2L*D_*F_];
__device__ __align__(256) __nv_bfloat16 g_w1t [2L*D_*F_];
__device__ float g_bqkv[QKVN];

// =================== PTX helpers ===========================================
__device__ __forceinline__ uint32_t smem_u32(const void* p){
    uint32_t a;
    asm("{ .reg .u64 t; cvta.to.shared.u64 t, %1; cvt.u32.u64 %0, t; }" : "=r"(a) : "l"(p));
    return a;
}
__device__ __forceinline__ void cpa16(uint32_t d, const void* s){
    asm volatile("cp.async.cg.shared.global [%0], [%1], 16;" :: "r"(d), "l"(s));
}
#define CP_COMMIT() asm volatile("cp.async.commit_group;" ::: "memory")

__device__ __forceinline__ void ldsm4(uint32_t* r, uint32_t addr){
    asm volatile("ldmatrix.sync.aligned.m8n8.x4.shared.b16 {%0,%1,%2,%3}, [%4];"
                 : "=r"(r[0]), "=r"(r[1]), "=r"(r[2]), "=r"(r[3]) : "r"(addr));
}
__device__ __forceinline__ void ldsm4t(uint32_t* r, uint32_t addr){
    asm volatile("ldmatrix.sync.aligned.m8n8.x4.trans.shared.b16 {%0,%1,%2,%3}, [%4];"
                 : "=r"(r[0]), "=r"(r[1]), "=r"(r[2]), "=r"(r[3]) : "r"(addr));
}
__device__ __forceinline__ void mma16816(float* c, const uint32_t* a, const uint32_t* b){
    asm volatile(
        "mma.sync.aligned.m16n8k16.row.col.f32.bf16.bf16.f32 "
        "{%0,%1,%2,%3}, {%4,%5,%6,%7}, {%8,%9}, {%0,%1,%2,%3};"
        : "+f"(c[0]), "+f"(c[1]), "+f"(c[2]), "+f"(c[3])
        : "r"(a[0]), "r"(a[1]), "r"(a[2]), "r"(a[3]), "r"(b[0]), "r"(b[1]));
}
__device__ __forceinline__ float gelu_exact(float v){
    return 0.5f * v * (1.0f + erff(v * 0.70710678118654752f));
}
__device__ __forceinline__ uint32_t swz(uint32_t off){ return off ^ ((off >> 3) & 0x70); }
__device__ __forceinline__ uint32_t pkh(float x, float y){
    __nv_bfloat162 h; h.x = __float2bfloat16(x); h.y = __float2bfloat16(y);
    return *(uint32_t*)&h;
}
__device__ __forceinline__ uint32_t pkl(float x, float y){
    float rx = x - __bfloat162float(__float2bfloat16(x));
    float ry = y - __bfloat162float(__float2bfloat16(y));
    __nv_bfloat162 h; h.x = __float2bfloat16(rx); h.y = __float2bfloat16(ry);
    return *(uint32_t*)&h;
}

// =================== LayerNorm: warp per row, shuffle reductions ============
__global__ void __launch_bounds__(256)
ln_kernel(const float* __restrict__ x,
          const float* __restrict__ g,
          const float* __restrict__ be,
          __nv_bfloat16* __restrict__ out, long plane)
{
    const int w = threadIdx.x >> 5, l = threadIdx.x & 31;
    const long row = (long)blockIdx.x * 8 + w;
    const float* xr = x + row * D_;

    float4 v[6];
    float s = 0.f;
    #pragma unroll
    for (int i = 0; i < 6; i++) {
        v[i] = *(const float4*)(xr + i * 128 + l * 4);
        s += v[i].x + v[i].y + v[i].z + v[i].w;
    }
    #pragma unroll
    for (int o = 16; o > 0; o >>= 1) s += __shfl_xor_sync(0xFFFFFFFFu, s, o);
    const float mu = s * (1.0f / D_);

    float vs = 0.f;
    #pragma unroll
    for (int i = 0; i < 6; i++) {
        float a = v[i].x - mu, b2 = v[i].y - mu, c = v[i].z - mu, d = v[i].w - mu;
        vs += a*a + b2*b2 + c*c + d*d;
    }
    #pragma unroll
    for (int o = 16; o > 0; o >>= 1) vs += __shfl_xor_sync(0xFFFFFFFFu, vs, o);
    const float inv = rsqrtf(vs * (1.0f / D_) + 1e-5f);

    __nv_bfloat16* orow = out + row * D_;
    #pragma unroll
    for (int i = 0; i < 6; i++) {
        const int col = i * 128 + l * 4;
        float4 gg = *(const float4*)(g  + col);
        float4 bb = *(const float4*)(be + col);
        float y0 = (v[i].x - mu) * inv * gg.x + bb.x;
        float y1 = (v[i].y - mu) * inv * gg.y + bb.y;
        float y2 = (v[i].z - mu) * inv * gg.z + bb.z;
        float y3 = (v[i].w - mu) * inv * gg.w + bb.w;
        uint2 hp; hp.x = pkh(y0, y1); hp.y = pkh(y2, y3);
        *(uint2*)(orow + col) = hp;
        uint2 lp; lp.x = pkl(y0, y1); lp.y = pkl(y2, y3);
        *(uint2*)(orow + plane + col) = lp;
    }
}

// =================== Weight transpose + split (fp32 in) =====================
__global__ void tsplit_kernel(const float* __restrict__ in, __nv_bfloat16* __restrict__ out,
                              int ldin, int ldout, long plane)
{
    __shared__ float t[32][33];
    const int c0 = blockIdx.x * 32, r0 = blockIdx.y * 32;
    const int tx = threadIdx.x, ty = threadIdx.y;
    #pragma unroll
    for (int i = 0; i < 32; i += 8)
        t[ty+i][tx] = in[(long)(r0+ty+i) * ldin + c0 + tx];
    __syncthreads();
    #pragma unroll
    for (int i = 0; i < 32; i += 8) {
        float v = t[tx][ty+i];
        __nv_bfloat16 h = __float2bfloat16(v);
        long o = (long)(c0+ty+i) * ldout + r0 + tx;
        out[o] = h;
        out[o + plane] = __float2bfloat16(v - __bfloat162float(h));
    }
}

__global__ void cat_bias(const float* __restrict__ a, const float* __restrict__ k,
                         const float* __restrict__ v, float* __restrict__ o)
{
    int i = blockIdx.x * 256 + threadIdx.x;
    if (i < QKVN)
        o[i] = (i < D_) ? a[i] : (i < 2*D_) ? k[i - D_] : v[i - 2*D_];
}

// =================== GELU + split combine (for MLP1 split-K) ================
// out = split_bf16(gelu(a + b + bias[col])); element i over [M, F]
__global__ void __launch_bounds__(256)
gelu_split(const float* __restrict__ a, const float* __restrict__ b,
           const float* __restrict__ bias, __nv_bfloat16* __restrict__ out, long plane)
{
    const long i0 = ((long)blockIdx.x * 256 + threadIdx.x) * 4;
    const int col = (int)(i0 % F_);
    float4 va = *(const float4*)(a + i0);
    float4 vb = *(const float4*)(b + i0);
    float4 bs = *(const float4*)(bias + col);
    float y0 = gelu_exact(va.x + vb.x + bs.x);
    float y1 = gelu_exact(va.y + vb.y + bs.y);
    float y2 = gelu_exact(va.z + vb.z + bs.z);
    float y3 = gelu_exact(va.w + vb.w + bs.w);
    uint2 hp; hp.x = pkh(y0, y1); hp.y = pkh(y2, y3);
    *(uint2*)(out + i0) = hp;
    uint2 lp; lp.x = pkl(y0, y1); lp.y = pkl(y2, y3);
    *(uint2*)(out + plane + i0) = lp;
}

// =================== HMMA GEMM, 3-stage pipeline, 2 CTAs/SM ================
// D[M,N] = epilogue(A @ B^T + bias). Split planes, 3 passes (hi.hi, hi.lo, lo.hi).
// CTA 128x128, BK=64, 8 warps 4x2, warp tile 32x64. Split-K over blockIdx.z.
// EPI 0: fp32 C[z-buffer] = v            (planeC = z-buffer stride)
// EPI 3: split-bf16 C = v + bias | EPI 4: split-bf16 C = gelu(v + bias)
// EPI 5: fp32 atomicAdd(C, v [+ bias if z==0])
template<int EPI>
__global__ void __launch_bounds__(256, 2)
gemm_mma(const __nv_bfloat16* __restrict__ A, const __nv_bfloat16* __restrict__ B,
         const float* __restrict__ bias, void* __restrict__ Cv,
         int K, int lda, int ldb, int ldc,
         long planeA, long planeB, long planeC)
{
    extern __shared__ char sm[];
    constexpr int ABYTES = 128 * 128;
    constexpr int BBYTES = 128 * 128;
    constexpr int STG = ABYTES + BBYTES;

    const uint32_t smb = (smem_u32(sm) + 127) & ~127u;

    const int tid = threadIdx.x;
    const int wid = tid >> 5, l = tid & 31;
    const int wm = (wid & 3) * 32;
    const int wn = (wid >> 2) * 64;

    const long bm = (long)blockIdx.y * 128;
    const long bn = (long)blockIdx.x * 128;
    const long koff = (long)blockIdx.z * K;

    float* Cf = (float*)Cv;
    if (EPI == 0) Cf += (long)blockIdx.z * planeC;
    __nv_bfloat16* Cb = (__nv_bfloat16*)Cv;

    const int kch = K / 64;
    const int NC = 3 * kch;

    float acc[2][8][4];
    #pragma unroll
    for (int i = 0; i < 2; i++)
        #pragma unroll
        for (int j = 0; j < 8; j++)
            #pragma unroll
            for (int q = 0; q < 4; q++) acc[i][j][q] = 0.f;

    auto load_chunk = [&](int c, int st) {
        const int p  = c / kch;
        const long kk = koff + (long)(c - p * kch) * 64;
        const __nv_bfloat16* Ap = A + ((p == 2) ? planeA : 0) + kk;
        const __nv_bfloat16* Bp = B + ((p == 1) ? planeB : 0) + kk;
        const uint32_t sA = smb + st * STG;
        const uint32_t sB = sA + ABYTES;
        #pragma unroll
        for (int j = 0; j < 4; j++) {
            int idx = tid * 4 + j;
            int row = idx >> 3, c16 = (idx & 7) * 16;
            cpa16(sA + swz(row * 128 + c16),
                  (const char*)(Ap + (bm + row) * lda) + c16);
        }
        #pragma unroll
        for (int j = 0; j < 4; j++) {
            int idx = tid * 4 + j;
            int row = idx >> 3, c16 = (idx & 7) * 16;
            cpa16(sB + swz(row * 128 + c16),
                  (const char*)(Bp + (bn + row) * ldb) + c16);
        }
        CP_COMMIT();
    };

    auto compute = [&](int st) {
        const uint32_t bA = smb + st * STG;
        const uint32_t bB = bA + ABYTES;
        #pragma unroll
        for (int kk2 = 0; kk2 < 4; kk2++) {
            uint32_t a[2][4];
            #pragma unroll
            for (int tm = 0; tm < 2; tm++) {
                int row = wm + tm * 16 + (l & 15);
                uint32_t off = row * 128 + kk2 * 32 + ((l >> 4) * 16);
                ldsm4(a[tm], bA + swz(off));
            }
            #pragma unroll
            for (int nb = 0; nb < 4; nb++) {
                uint32_t b[4];
                int rowB = wn + nb * 16 + (l & 7) + ((l >> 4) << 3);
                uint32_t off = rowB * 128 + kk2 * 32 + (((l >> 3) & 1) * 16);
                ldsm4(b, bB + swz(off));
                #pragma unroll
                for (int tm = 0; tm < 2; tm++) {
                    mma16816(acc[tm][2*nb],   a[tm], b);
                    mma16816(acc[tm][2*nb+1], a[tm], b + 2);
                }
            }
        }
    };

    load_chunk(0, 0);
    load_chunk(1, 1);
    for (int c = 0; c < NC; c++) {
        if (c < NC - 1) asm volatile("cp.async.wait_group 1;" ::: "memory");
        else            asm volatile("cp.async.wait_group 0;" ::: "memory");
        __syncthreads();
        if (c + 2 < NC) load_chunk(c + 2, (c + 2) % 3);
        compute(c % 3);
    }

    // -------- epilogue --------
    const bool addb = (EPI != 5) || (blockIdx.z == 0);
    #pragma unroll
    for (int tm = 0; tm < 2; tm++) {
        #pragma unroll
        for (int nf = 0; nf < 8; nf++) {
            const long col = bn + wn + nf * 8 + (l & 3) * 2;
            const float bb0 = (bias && addb) ? bias[col]     : 0.f;
            const float bb1 = (bias && addb) ? bias[col + 1] : 0.f;
            #pragma unroll
            for (int h = 0; h < 2; h++) {
                const long row = bm + wm + tm * 16 + (l >> 2) + h * 8;
                float v0 = acc[tm][nf][2*h]     + bb0;
                float v1 = acc[tm][nf][2*h + 1] + bb1;
                if (EPI == 4) { v0 = gelu_exact(v0); v1 = gelu_exact(v1); }
                const long idx = row * (long)ldc + col;
                if (EPI == 0) {
                    float2 t; t.x = v0; t.y = v1;
                    *(float2*)(Cf + idx) = t;
                } else if (EPI == 5) {
                    atomicAdd(Cf + idx, v0);
                    atomicAdd(Cf + idx + 1, v1);
                } else {
                    __nv_bfloat16 h0 = __float2bfloat16(v0);
                    __nv_bfloat16 h1 = __float2bfloat16(v1);
                    __nv_bfloat162 hv; hv.x = h0; hv.y = h1;
                    *(__nv_bfloat162*)(Cb + idx) = hv;
                    __nv_bfloat162 lv;
                    lv.x = __float2bfloat16(v0 - __bfloat162float(h0));
                    lv.y = __float2bfloat16(v1 - __bfloat162float(h1));
                    *(__nv_bfloat162*)(Cb + idx + planeC) = lv;
                }
            }
        }
    }
}

// =================== Fused flash attention =================================
// grid (N_/128, B_*H_). 8 warps x 16 queries. K and V both streamed straight
// from the qkv buffer in 64-key chunks (2-stage cp.async, 2 CTAs/SM).
// V consumed via ldmatrix.trans (no pre-transpose). Online softmax, split-bf16
// P@V, residual x += out fused.
__global__ void __launch_bounds__(256, 2)
flash_attn(const __nv_bfloat16* __restrict__ qkv, float* __restrict__ x, long planeQ)
{
    extern __shared__ char sm[];
    const uint32_t smb = (smem_u32(sm) + 127) & ~127u;
    const uint32_t Qb = smb;             // Q: hi 16K + lo 16K
    const uint32_t St = smb + 32768;     // 2 stages x 32K (Khi 8K, Klo 8K, Vhi 8K, Vlo 8K)

    const int tid = threadIdx.x, wid = tid >> 5, l = tid & 31;
    const int qt = blockIdx.x, z = blockIdx.y;
    const int b = z / H_, h = z % H_;
    const long tokq = (long)b * N_ + qt * 128;

    // Q tile loads (committed with chunk 0)
    #pragma unroll
    for (int p = 0; p < 2; p++)
        #pragma unroll
        for (int j = 0; j < 4; j++) {
            int idx = tid * 4 + j;
            int row = idx >> 3, c16 = idx & 7;
            cpa16(Qb + p*16384 + swz(row*128 + c16*16),
                  qkv + p*planeQ + (tokq + row)*QKVN + h*HD_ + c16*8);
        }

    auto load_kv = [&](int c, int st) {
        const uint32_t base = St + st * 32768;
        #pragma unroll
        for (int p = 0; p < 2; p++)
            #pragma unroll
            for (int j = 0; j < 2; j++) {
                int idx = tid * 2 + j;
                int row = idx >> 3, c16 = idx & 7;
                const long tok = (long)b * N_ + c * 64 + row;
                cpa16(base + p*8192 + swz(row*128 + c16*16),
                      qkv + p*planeQ + tok*QKVN + D_ + h*HD_ + c16*8);
                cpa16(base + 16384 + p*8192 + swz(row*128 + c16*16),
                      qkv + p*planeQ + tok*QKVN + 2*D_ + h*HD_ + c16*8);
            }
        CP_COMMIT();
    };

    load_kv(0, 0);
    load_kv(1, 1);

    float o[8][4];
    #pragma unroll
    for (int i = 0; i < 8; i++)
        #pragma unroll
        for (int q = 0; q < 4; q++) o[i][q] = 0.f;
    float m0 = -1e30f, m1 = -1e30f, rs0 = 0.f, rs1 = 0.f;

    const int NCH = N_ / 64;   // 8
    for (int c = 0; c < NCH; c++) {
        if (c < NCH - 1) asm volatile("cp.async.wait_group 1;" ::: "memory");
        else             asm volatile("cp.async.wait_group 0;" ::: "memory");
        __syncthreads();

        const uint32_t Kst = St + (c & 1) * 32768;
        const uint32_t Vst = Kst + 16384;

        // ---- S = (Q @ K^T) * 0.125, split 3-pass ----
        float s[8][4];
        #pragma unroll
        for (int i = 0; i < 8; i++)
            #pragma unroll
            for (int q = 0; q < 4; q++) s[i][q] = 0.f;

        #pragma unroll
        for (int kk = 0; kk < 4; kk++) {
            uint32_t ah[4], al[4];
            {
                int row = wid * 16 + (l & 15);
                uint32_t off = row * 128 + kk * 32 + ((l >> 4) * 16);
                ldsm4(ah, Qb + swz(off));
                ldsm4(al, Qb + 16384 + swz(off));
            }
            #pragma unroll
            for (int nb = 0; nb < 4; nb++) {
                int rowB = nb * 16 + (l & 7) + ((l >> 4) << 3);
                uint32_t off = rowB * 128 + kk * 32 + (((l >> 3) & 1) * 16);
                uint32_t bh[4], bl[4];
                ldsm4(bh, Kst + swz(off));
                ldsm4(bl, Kst + 8192 + swz(off));
                mma16816(s[2*nb],   ah, bh); mma16816(s[2*nb+1], ah, bh + 2);
                mma16816(s[2*nb],   ah, bl); mma16816(s[2*nb+1], ah, bl + 2);
                mma16816(s[2*nb],   al, bh); mma16816(s[2*nb+1], al, bh + 2);
            }
        }
        #pragma unroll
        for (int i = 0; i < 8; i++)
            #pragma unroll
            for (int q = 0; q < 4; q++) s[i][q] *= 0.125f;

        // ---- online softmax ----
        float mx0 = -1e30f, mx1 = -1e30f;
        #pragma unroll
        for (int i = 0; i < 8; i++) {
            mx0 = fmaxf(mx0, fmaxf(s[i][0], s[i][1]));
            mx1 = fmaxf(mx1, fmaxf(s[i][2], s[i][3]));
        }
        mx0 = fmaxf(mx0, __shfl_xor_sync(0xFFFFFFFFu, mx0, 1));
        mx0 = fmaxf(mx0, __shfl_xor_sync(0xFFFFFFFFu, mx0, 2));
        mx1 = fmaxf(mx1, __shfl_xor_sync(0xFFFFFFFFu, mx1, 1));
        mx1 = fmaxf(mx1, __shfl_xor_sync(0xFFFFFFFFu, mx1, 2));
        float nm0 = fmaxf(m0, mx0), nm1 = fmaxf(m1, mx1);
        float sc0 = __expf(m0 - nm0), sc1 = __expf(m1 - nm1);
        m0 = nm0; m1 = nm1;

        float sum0 = 0.f, sum1 = 0.f;
        #pragma unroll
        for (int i = 0; i < 8; i++) {
            s[i][0] = __expf(s[i][0] - m0);
            s[i][1] = __expf(s[i][1] - m0);
            s[i][2] = __expf(s[i][2] - m1);
            s[i][3] = __expf(s[i][3] - m1);
            sum0 += s[i][0] + s[i][1];
            sum1 += s[i][2] + s[i][3];
        }
        sum0 += __shfl_xor_sync(0xFFFFFFFFu, sum0, 1);
        sum0 += __shfl_xor_sync(0xFFFFFFFFu, sum0, 2);
        sum1 += __shfl_xor_sync(0xFFFFFFFFu, sum1, 1);
        sum1 += __shfl_xor_sync(0xFFFFFFFFu, sum1, 2);
        rs0 = rs0 * sc0 + sum0;
        rs1 = rs1 * sc1 + sum1;

        #pragma unroll
        for (int i = 0; i < 8; i++) {
            o[i][0] *= sc0; o[i][1] *= sc0;
            o[i][2] *= sc1; o[i][3] *= sc1;
        }

        // ---- O += P @ V (V via ldmatrix.trans), split 3-pass ----
        #pragma unroll
        for (int kc = 0; kc < 4; kc++) {
            uint32_t ah[4], al[4];
            ah[0] = pkh(s[2*kc][0],   s[2*kc][1]);
            ah[1] = pkh(s[2*kc][2],   s[2*kc][3]);
            ah[2] = pkh(s[2*kc+1][0], s[2*kc+1][1]);
            ah[3] = pkh(s[2*kc+1][2], s[2*kc+1][3]);
            al[0] = pkl(s[2*kc][0],   s[2*kc][1]);
            al[1] = pkl(s[2*kc][2],   s[2*kc][3]);
            al[2] = pkl(s[2*kc+1][0], s[2*kc+1][1]);
            al[3] = pkl(s[2*kc+1][2], s[2*kc+1][3]);
            #pragma unroll
            for (int nb = 0; nb < 4; nb++) {
                // V stored [64 keys x 64 hd]; trans-ldsm: rows = keys
                uint32_t off = (kc*16 + (l & 15)) * 128 + nb*32 + ((l >> 4) * 16);
                uint32_t bh[4], bl[4];
                ldsm4t(bh, Vst + swz(off));
                ldsm4t(bl, Vst + 8192 + swz(off));
                mma16816(o[2*nb],   ah, bh); mma16816(o[2*nb+1], ah, bh + 2);
                mma16816(o[2*nb],   ah, bl); mma16816(o[2*nb+1], ah, bl + 2);
                mma16816(o[2*nb],   al, bh); mma16816(o[2*nb+1], al, bh + 2);
            }
        }

        __syncthreads();                        // all warps done with stage c&1
        if (c + 2 < NCH) load_kv(c + 2, c & 1);
    }

    // ---- epilogue: x += O / rowsum ----
    const float inv0 = 1.f / rs0, inv1 = 1.f / rs1;
    const long tok0 = tokq + wid * 16 + (l >> 2);
    const long col = h * HD_ + (l & 3) * 2;
    #pragma unroll
    for (int nf = 0; nf < 8; nf++) {
        float2* p0 = (float2*)(x + tok0 * D_ + col + nf * 8);
        float2 t0 = *p0;
        t0.x += o[nf][0] * inv0; t0.y += o[nf][1] * inv0;
        *p0 = t0;
        float2* p1 = (float2*)(x + (tok0 + 8) * D_ + col + nf * 8);
        float2 t1 = *p1;
        t1.x += o[nf][2] * inv1; t1.y += o[nf][3] * inv1;
        *p1 = t1;
    }
}

// =================== driver ================================================
extern "C" void kernel_launch(void* const* d_in, const int* in_sizes, int n_in,
                              void* d_out, int out_size)
{
    const float* x0  = (const float*)d_in[0];
    const float* Wq  = (const float*)d_in[1];
    const float* bq  = (const float*)d_in[2];
    const float* Wk  = (const float*)d_in[3];
    const float* bk  = (const float*)d_in[4];
    const float* Wv  = (const float*)d_in[5];
    const float* bv  = (const float*)d_in[6];
    const float* g1  = (const float*)d_in[7];
    const float* be1 = (const float*)d_in[8];
    const float* g2  = (const float*)d_in[9];
    const float* be2 = (const float*)d_in[10];
    const float* W0  = (const float*)d_in[11];
    const float* b0  = (const float*)d_in[12];
    const float* W1  = (const float*)d_in[13];
    const float* b1  = (const float*)d_in[14];

    float* x = (float*)d_out;

    __nv_bfloat16 *lns, *qkvs, *ffs, *wqkv, *w0t, *w1t;
    float *bqkv, *ffw;
    cudaGetSymbolAddress((void**)&lns,  g_lns);
    cudaGetSymbolAddress((void**)&qkvs, g_qkvs);
    cudaGetSymbolAddress((void**)&ffs,  g_ffs);
    cudaGetSymbolAddress((void**)&ffw,  g_ffw);
    cudaGetSymbolAddress((void**)&wqkv, g_wqkv);
    cudaGetSymbolAddress((void**)&w0t,  g_w0t);
    cudaGetSymbolAddress((void**)&w1t,  g_w1t);
    cudaGetSymbolAddress((void**)&bqkv, g_bqkv);

    const int SMG = 3 * (128*128 + 128*128) + 256;   // 98560
    const int SMF = 32768 + 2 * 32768 + 256;          // 98560
    cudaFuncSetAttribute(gemm_mma<0>, cudaFuncAttributeMaxDynamicSharedMemorySize, SMG);
    cudaFuncSetAttribute(gemm_mma<3>, cudaFuncAttributeMaxDynamicSharedMemorySize, SMG);
    cudaFuncSetAttribute(gemm_mma<5>, cudaFuncAttributeMaxDynamicSharedMemorySize, SMG);
    cudaFuncSetAttribute(flash_attn,  cudaFuncAttributeMaxDynamicSharedMemorySize, SMF);

    cudaMemcpyAsync(x, x0, sizeof(float)*M_*D_, cudaMemcpyDeviceToDevice);

    // ---- weight preprocessing (once per launch) ----
    dim3 tb(32, 8);
    const long WQKV = (long)QKVN * D_;
    tsplit_kernel<<<dim3(D_/32, D_/32), tb>>>(Wq, wqkv,                 D_, D_, WQKV);
    tsplit_kernel<<<dim3(D_/32, D_/32), tb>>>(Wk, wqkv + (long)D_*D_,   D_, D_, WQKV);
    tsplit_kernel<<<dim3(D_/32, D_/32), tb>>>(Wv, wqkv + (long)2*D_*D_, D_, D_, WQKV);
    tsplit_kernel<<<dim3(F_/32, D_/32), tb>>>(W0, w0t, F_, D_, (long)D_*F_);
    tsplit_kernel<<<dim3(D_/32, F_/32), tb>>>(W1, w1t, D_, F_, (long)D_*F_);
    cat_bias<<<9, 256>>>(bq, bk, bv, bqkv);

    const long MD   = (long)M_ * D_;
    const long MQ   = (long)M_ * QKVN;
    const long MF   = (long)M_ * F_;
    const long WDF  = (long)D_ * F_;

    for (int blk = 0; blk < NBLOCKS; blk++) {
        // ---- attention ----
        ln_kernel<<<M_/8, 256>>>(x, g1, be1, lns, MD);

        gemm_mma<3><<<dim3(QKVN/128, M_/128), 256, SMG>>>(
            lns, wqkv, bqkv, qkvs, D_, D_, D_, QKVN, MD, WQKV, MQ);

        flash_attn<<<dim3(N_/128, B_*H_), 256, SMF>>>(qkvs, x, MQ);

        // ---- MLP ----
        ln_kernel<<<M_/8, 256>>>(x, g2, be2, lns, MD);

        // MLP1: split-K x2 into two fp32 buffers (fills the machine better)
        gemm_mma<0><<<dim3(F_/128, M_/128, 2), 256, SMG>>>(
            lns, w0t, nullptr, ffw, D_/2, D_, D_, F_, MD, WDF, MF);

        // combine + bias + GELU + split
        gelu_split<<<(int)(MF/1024), 256>>>(ffw, ffw + MF, b0, ffs, MF);

        // MLP2: split-K x3 (288 CTAs = one full wave), atomic residual into x
        gemm_mma<5><<<dim3(D_/128, M_/128, 3), 256, SMG>>>(
            ffs, w1t, b1, x, F_/3, F_, F_, D_, MF, WDF, 0);
    }
    (void)in_sizes; (void)n_in; (void)out_size;
}

// round 8
// speedup vs baseline: 4.3425x; 1.0257x over previous
#include <cuda_runtime.h>
#include <cuda_bf16.h>
#include <math.h>
#include <stdint.h>

// Problem constants
#define B_  4
#define N_  512
#define D_  768
#define F_  3072
#define H_  12
#define HD_ 64
#define M_  (B_*N_)   // 2048 tokens
#define NBLOCKS 12
#define QKVN (3*D_)   // 2304

// =================== scratch (static device globals) ========================
// split-bf16 planes: [hi plane][lo plane], plane offset = element count
__device__ __align__(256) __nv_bfloat16 g_lns [2L*M_*D_];
__device__ __align__(256) __nv_bfloat16 g_qkvs[2L*M_*QKVN];
__device__ __align__(256) __nv_bfloat16 g_ffs [2L*M_*F_];
__device__ __align__(256) float         g_ffw [3L*M_*F_];   // split-K fp32 partials
__device__ __align__(256) __nv_bfloat16 g_wqkv[2L*QKVN*D_];
__device__ __align__(256) __nv_bfloat16 g_w0t [2L*D_*F_];
__device__ __align__(256) __nv_bfloat16 g_w1t [2L*D_*F_];
__device__ float g_bqkv[QKVN];

// =================== PTX helpers ===========================================
__device__ __forceinline__ uint32_t smem_u32(const void* p){
    uint32_t a;
    asm("{ .reg .u64 t; cvta.to.shared.u64 t, %1; cvt.u32.u64 %0, t; }" : "=r"(a) : "l"(p));
    return a;
}
__device__ __forceinline__ void cpa16(uint32_t d, const void* s){
    asm volatile("cp.async.cg.shared.global [%0], [%1], 16;" :: "r"(d), "l"(s));
}
#define CP_COMMIT() asm volatile("cp.async.commit_group;" ::: "memory")

__device__ __forceinline__ void ldsm4(uint32_t* r, uint32_t addr){
    asm volatile("ldmatrix.sync.aligned.m8n8.x4.shared.b16 {%0,%1,%2,%3}, [%4];"
                 : "=r"(r[0]), "=r"(r[1]), "=r"(r[2]), "=r"(r[3]) : "r"(addr));
}
__device__ __forceinline__ void ldsm4t(uint32_t* r, uint32_t addr){
    asm volatile("ldmatrix.sync.aligned.m8n8.x4.trans.shared.b16 {%0,%1,%2,%3}, [%4];"
                 : "=r"(r[0]), "=r"(r[1]), "=r"(r[2]), "=r"(r[3]) : "r"(addr));
}
__device__ __forceinline__ void mma16816(float* c, const uint32_t* a, const uint32_t* b){
    asm volatile(
        "mma.sync.aligned.m16n8k16.row.col.f32.bf16.bf16.f32 "
        "{%0,%1,%2,%3}, {%4,%5,%6,%7}, {%8,%9}, {%0,%1,%2,%3};"
        : "+f"(c[0]), "+f"(c[1]), "+f"(c[2]), "+f"(c[3])
        : "r"(a[0]), "r"(a[1]), "r"(a[2]), "r"(a[3]), "r"(b[0]), "r"(b[1]));
}
__device__ __forceinline__ float gelu_exact(float v){
    return 0.5f * v * (1.0f + erff(v * 0.70710678118654752f));
}
__device__ __forceinline__ uint32_t swz(uint32_t off){ return off ^ ((off >> 3) & 0x70); }
__device__ __forceinline__ uint32_t pkh(float x, float y){
    __nv_bfloat162 h; h.x = __float2bfloat16(x); h.y = __float2bfloat16(y);
    return *(uint32_t*)&h;
}
__device__ __forceinline__ uint32_t pkl(float x, float y){
    float rx = x - __bfloat162float(__float2bfloat16(x));
    float ry = y - __bfloat162float(__float2bfloat16(y));
    __nv_bfloat162 h; h.x = __float2bfloat16(rx); h.y = __float2bfloat16(ry);
    return *(uint32_t*)&h;
}

// =================== LayerNorm: warp per row, shuffle reductions ============
__global__ void __launch_bounds__(256)
ln_kernel(const float* __restrict__ x,
          const float* __restrict__ g,
          const float* __restrict__ be,
          __nv_bfloat16* __restrict__ out, long plane)
{
    const int w = threadIdx.x >> 5, l = threadIdx.x & 31;
    const long row = (long)blockIdx.x * 8 + w;
    const float* xr = x + row * D_;

    float4 v[6];
    float s = 0.f;
    #pragma unroll
    for (int i = 0; i < 6; i++) {
        v[i] = *(const float4*)(xr + i * 128 + l * 4);
        s += v[i].x + v[i].y + v[i].z + v[i].w;
    }
    #pragma unroll
    for (int o = 16; o > 0; o >>= 1) s += __shfl_xor_sync(0xFFFFFFFFu, s, o);
    const float mu = s * (1.0f / D_);

    float vs = 0.f;
    #pragma unroll
    for (int i = 0; i < 6; i++) {
        float a = v[i].x - mu, b2 = v[i].y - mu, c = v[i].z - mu, d = v[i].w - mu;
        vs += a*a + b2*b2 + c*c + d*d;
    }
    #pragma unroll
    for (int o = 16; o > 0; o >>= 1) vs += __shfl_xor_sync(0xFFFFFFFFu, vs, o);
    const float inv = rsqrtf(vs * (1.0f / D_) + 1e-5f);

    __nv_bfloat16* orow = out + row * D_;
    #pragma unroll
    for (int i = 0; i < 6; i++) {
        const int col = i * 128 + l * 4;
        float4 gg = *(const float4*)(g  + col);
        float4 bb = *(const float4*)(be + col);
        float y0 = (v[i].x - mu) * inv * gg.x + bb.x;
        float y1 = (v[i].y - mu) * inv * gg.y + bb.y;
        float y2 = (v[i].z - mu) * inv * gg.z + bb.z;
        float y3 = (v[i].w - mu) * inv * gg.w + bb.w;
        uint2 hp; hp.x = pkh(y0, y1); hp.y = pkh(y2, y3);
        *(uint2*)(orow + col) = hp;
        uint2 lp; lp.x = pkl(y0, y1); lp.y = pkl(y2, y3);
        *(uint2*)(orow + plane + col) = lp;
    }
}

// =================== Weight transpose + split (batched) =====================
__device__ __forceinline__ void tsplit_tile(const float* __restrict__ in,
                                            __nv_bfloat16* __restrict__ out,
                                            int ldin, int ldout, long plane,
                                            int c0, int r0, int tx, int ty,
                                            float (*t)[33])
{
    #pragma unroll
    for (int i = 0; i < 32; i += 8)
        t[ty+i][tx] = in[(long)(r0+ty+i) * ldin + c0 + tx];
    __syncthreads();
    #pragma unroll
    for (int i = 0; i < 32; i += 8) {
        float v = t[tx][ty+i];
        __nv_bfloat16 h = __float2bfloat16(v);
        long o = (long)(c0+ty+i) * ldout + r0 + tx;
        out[o] = h;
        out[o + plane] = __float2bfloat16(v - __bfloat162float(h));
    }
}

// one launch: Wq/Wk/Wv (z = 0/1/2), each [D_, D_] -> wqkv + z*D_*D_
__global__ void tsplit_qkv(const float* __restrict__ Wq, const float* __restrict__ Wk,
                           const float* __restrict__ Wv, __nv_bfloat16* __restrict__ out)
{
    __shared__ float t[32][33];
    const int z = blockIdx.z;
    const float* in = (z == 0) ? Wq : (z == 1) ? Wk : Wv;
    tsplit_tile(in, out + (long)z * D_ * D_, D_, D_, (long)QKVN * D_,
                blockIdx.x * 32, blockIdx.y * 32, threadIdx.x, threadIdx.y, t);
}

// one launch: W0 (z=0, [D_,F_] -> w0t [F_,D_]) and W1 (z=1, [F_,D_] -> w1t [D_,F_])
__global__ void tsplit_mlp(const float* __restrict__ W0, const float* __restrict__ W1,
                           __nv_bfloat16* __restrict__ w0t, __nv_bfloat16* __restrict__ w1t)
{
    __shared__ float t[32][33];
    const int z = blockIdx.z;
    const int bx = z ? blockIdx.y : blockIdx.x;   // input-col block
    const int by = z ? blockIdx.x : blockIdx.y;   // input-row block
    if (z == 0)
        tsplit_tile(W0, w0t, F_, D_, (long)D_ * F_, bx * 32, by * 32,
                    threadIdx.x, threadIdx.y, t);
    else
        tsplit_tile(W1, w1t, D_, F_, (long)D_ * F_, bx * 32, by * 32,
                    threadIdx.x, threadIdx.y, t);
}

__global__ void cat_bias(const float* __restrict__ a, const float* __restrict__ k,
                         const float* __restrict__ v, float* __restrict__ o)
{
    int i = blockIdx.x * 256 + threadIdx.x;
    if (i < QKVN)
        o[i] = (i < D_) ? a[i] : (i < 2*D_) ? k[i - D_] : v[i - 2*D_];
}

// =================== GELU + split combine (MLP1 split-K x3) =================
__global__ void __launch_bounds__(256)
gelu_split(const float* __restrict__ a, const float* __restrict__ b,
           const float* __restrict__ c,
           const float* __restrict__ bias, __nv_bfloat16* __restrict__ out, long plane)
{
    const long i0 = ((long)blockIdx.x * 256 + threadIdx.x) * 4;
    const int col = (int)(i0 % F_);
    float4 va = *(const float4*)(a + i0);
    float4 vb = *(const float4*)(b + i0);
    float4 vc = *(const float4*)(c + i0);
    float4 bs = *(const float4*)(bias + col);
    float y0 = gelu_exact(va.x + vb.x + vc.x + bs.x);
    float y1 = gelu_exact(va.y + vb.y + vc.y + bs.y);
    float y2 = gelu_exact(va.z + vb.z + vc.z + bs.z);
    float y3 = gelu_exact(va.w + vb.w + vc.w + bs.w);
    uint2 hp; hp.x = pkh(y0, y1); hp.y = pkh(y2, y3);
    *(uint2*)(out + i0) = hp;
    uint2 lp; lp.x = pkl(y0, y1); lp.y = pkl(y2, y3);
    *(uint2*)(out + plane + i0) = lp;
}

// =================== HMMA GEMM, 3-stage pipeline, 2 CTAs/SM ================
// D[M,N] = epilogue(A @ B^T + bias). Split planes, 3 passes (hi.hi, hi.lo, lo.hi).
// CTA 128x128, BK=64, 8 warps 4x2, warp tile 32x64. Split-K over blockIdx.z.
// EPI 0: fp32 C[z-buffer] = v            (planeC = z-buffer stride)
// EPI 3: split-bf16 C = v + bias
// EPI 5: fp32 atomicAdd(C, v [+ bias if z==0])
template<int EPI>
__global__ void __launch_bounds__(256, 2)
gemm_mma(const __nv_bfloat16* __restrict__ A, const __nv_bfloat16* __restrict__ B,
         const float* __restrict__ bias, void* __restrict__ Cv,
         int K, int lda, int ldb, int ldc,
         long planeA, long planeB, long planeC)
{
    extern __shared__ char sm[];
    constexpr int ABYTES = 128 * 128;
    constexpr int BBYTES = 128 * 128;
    constexpr int STG = ABYTES + BBYTES;

    const uint32_t smb = (smem_u32(sm) + 127) & ~127u;

    const int tid = threadIdx.x;
    const int wid = tid >> 5, l = tid & 31;
    const int wm = (wid & 3) * 32;
    const int wn = (wid >> 2) * 64;

    const long bm = (long)blockIdx.y * 128;
    const long bn = (long)blockIdx.x * 128;
    const long koff = (long)blockIdx.z * K;

    float* Cf = (float*)Cv;
    if (EPI == 0) Cf += (long)blockIdx.z * planeC;
    __nv_bfloat16* Cb = (__nv_bfloat16*)Cv;

    const int kch = K / 64;
    const int NC = 3 * kch;

    float acc[2][8][4];
    #pragma unroll
    for (int i = 0; i < 2; i++)
        #pragma unroll
        for (int j = 0; j < 8; j++)
            #pragma unroll
            for (int q = 0; q < 4; q++) acc[i][j][q] = 0.f;

    auto load_chunk = [&](int c, int st) {
        const int p  = c / kch;
        const long kk = koff + (long)(c - p * kch) * 64;
        const __nv_bfloat16* Ap = A + ((p == 2) ? planeA : 0) + kk;
        const __nv_bfloat16* Bp = B + ((p == 1) ? planeB : 0) + kk;
        const uint32_t sA = smb + st * STG;
        const uint32_t sB = sA + ABYTES;
        #pragma unroll
        for (int j = 0; j < 4; j++) {
            int idx = tid * 4 + j;
            int row = idx >> 3, c16 = (idx & 7) * 16;
            cpa16(sA + swz(row * 128 + c16),
                  (const char*)(Ap + (bm + row) * lda) + c16);
        }
        #pragma unroll
        for (int j = 0; j < 4; j++) {
            int idx = tid * 4 + j;
            int row = idx >> 3, c16 = (idx & 7) * 16;
            cpa16(sB + swz(row * 128 + c16),
                  (const char*)(Bp + (bn + row) * ldb) + c16);
        }
        CP_COMMIT();
    };

    auto compute = [&](int st) {
        const uint32_t bA = smb + st * STG;
        const uint32_t bB = bA + ABYTES;
        #pragma unroll
        for (int kk2 = 0; kk2 < 4; kk2++) {
            uint32_t a[2][4];
            #pragma unroll
            for (int tm = 0; tm < 2; tm++) {
                int row = wm + tm * 16 + (l & 15);
                uint32_t off = row * 128 + kk2 * 32 + ((l >> 4) * 16);
                ldsm4(a[tm], bA + swz(off));
            }
            #pragma unroll
            for (int nb = 0; nb < 4; nb++) {
                uint32_t b[4];
                int rowB = wn + nb * 16 + (l & 7) + ((l >> 4) << 3);
                uint32_t off = rowB * 128 + kk2 * 32 + (((l >> 3) & 1) * 16);
                ldsm4(b, bB + swz(off));
                #pragma unroll
                for (int tm = 0; tm < 2; tm++) {
                    mma16816(acc[tm][2*nb],   a[tm], b);
                    mma16816(acc[tm][2*nb+1], a[tm], b + 2);
                }
            }
        }
    };

    load_chunk(0, 0);
    load_chunk(1, 1);
    for (int c = 0; c < NC; c++) {
        if (c < NC - 1) asm volatile("cp.async.wait_group 1;" ::: "memory");
        else            asm volatile("cp.async.wait_group 0;" ::: "memory");
        __syncthreads();
        if (c + 2 < NC) load_chunk(c + 2, (c + 2) % 3);
        compute(c % 3);
    }

    // -------- epilogue --------
    const bool addb = (EPI != 5) || (blockIdx.z == 0);
    #pragma unroll
    for (int tm = 0; tm < 2; tm++) {
        #pragma unroll
        for (int nf = 0; nf < 8; nf++) {
            const long col = bn + wn + nf * 8 + (l & 3) * 2;
            const float bb0 = (bias && addb) ? bias[col]     : 0.f;
            const float bb1 = (bias && addb) ? bias[col + 1] : 0.f;
            #pragma unroll
            for (int h = 0; h < 2; h++) {
                const long row = bm + wm + tm * 16 + (l >> 2) + h * 8;
                float v0 = acc[tm][nf][2*h]     + bb0;
                float v1 = acc[tm][nf][2*h + 1] + bb1;
                const long idx = row * (long)ldc + col;
                if (EPI == 0) {
                    float2 t; t.x = v0; t.y = v1;
                    *(float2*)(Cf + idx) = t;
                } else if (EPI == 5) {
                    atomicAdd(Cf + idx, v0);
                    atomicAdd(Cf + idx + 1, v1);
                } else {
                    __nv_bfloat16 h0 = __float2bfloat16(v0);
                    __nv_bfloat16 h1 = __float2bfloat16(v1);
                    __nv_bfloat162 hv; hv.x = h0; hv.y = h1;
                    *(__nv_bfloat162*)(Cb + idx) = hv;
                    __nv_bfloat162 lv;
                    lv.x = __float2bfloat16(v0 - __bfloat162float(h0));
                    lv.y = __float2bfloat16(v1 - __bfloat162float(h1));
                    *(__nv_bfloat162*)(Cb + idx + planeC) = lv;
                }
            }
        }
    }
}

// =================== Fused flash attention =================================
__global__ void __launch_bounds__(256, 2)
flash_attn(const __nv_bfloat16* __restrict__ qkv, float* __restrict__ x, long planeQ)
{
    extern __shared__ char sm[];
    const uint32_t smb = (smem_u32(sm) + 127) & ~127u;
    const uint32_t Qb = smb;             // Q: hi 16K + lo 16K
    const uint32_t St = smb + 32768;     // 2 stages x 32K (Khi 8K, Klo 8K, Vhi 8K, Vlo 8K)

    const int tid = threadIdx.x, wid = tid >> 5, l = tid & 31;
    const int qt = blockIdx.x, z = blockIdx.y;
    const int b = z / H_, h = z % H_;
    const long tokq = (long)b * N_ + qt * 128;

    // Q tile loads (committed with chunk 0)
    #pragma unroll
    for (int p = 0; p < 2; p++)
        #pragma unroll
        for (int j = 0; j < 4; j++) {
            int idx = tid * 4 + j;
            int row = idx >> 3, c16 = idx & 7;
            cpa16(Qb + p*16384 + swz(row*128 + c16*16),
                  qkv + p*planeQ + (tokq + row)*QKVN + h*HD_ + c16*8);
        }

    auto load_kv = [&](int c, int st) {
        const uint32_t base = St + st * 32768;
        #pragma unroll
        for (int p = 0; p < 2; p++)
            #pragma unroll
            for (int j = 0; j < 2; j++) {
                int idx = tid * 2 + j;
                int row = idx >> 3, c16 = idx & 7;
                const long tok = (long)b * N_ + c * 64 + row;
                cpa16(base + p*8192 + swz(row*128 + c16*16),
                      qkv + p*planeQ + tok*QKVN + D_ + h*HD_ + c16*8);
                cpa16(base + 16384 + p*8192 + swz(row*128 + c16*16),
                      qkv + p*planeQ + tok*QKVN + 2*D_ + h*HD_ + c16*8);
            }
        CP_COMMIT();
    };

    load_kv(0, 0);
    load_kv(1, 1);

    float o[8][4];
    #pragma unroll
    for (int i = 0; i < 8; i++)
        #pragma unroll
        for (int q = 0; q < 4; q++) o[i][q] = 0.f;
    float m0 = -1e30f, m1 = -1e30f, rs0 = 0.f, rs1 = 0.f;

    const int NCH = N_ / 64;   // 8
    for (int c = 0; c < NCH; c++) {
        if (c < NCH - 1) asm volatile("cp.async.wait_group 1;" ::: "memory");
        else             asm volatile("cp.async.wait_group 0;" ::: "memory");
        __syncthreads();

        const uint32_t Kst = St + (c & 1) * 32768;
        const uint32_t Vst = Kst + 16384;

        // ---- S = (Q @ K^T) * 0.125, split 3-pass ----
        float s[8][4];
        #pragma unroll
        for (int i = 0; i < 8; i++)
            #pragma unroll
            for (int q = 0; q < 4; q++) s[i][q] = 0.f;

        #pragma unroll
        for (int kk = 0; kk < 4; kk++) {
            uint32_t ah[4], al[4];
            {
                int row = wid * 16 + (l & 15);
                uint32_t off = row * 128 + kk * 32 + ((l >> 4) * 16);
                ldsm4(ah, Qb + swz(off));
                ldsm4(al, Qb + 16384 + swz(off));
            }
            #pragma unroll
            for (int nb = 0; nb < 4; nb++) {
                int rowB = nb * 16 + (l & 7) + ((l >> 4) << 3);
                uint32_t off = rowB * 128 + kk * 32 + (((l >> 3) & 1) * 16);
                uint32_t bh[4], bl[4];
                ldsm4(bh, Kst + swz(off));
                ldsm4(bl, Kst + 8192 + swz(off));
                mma16816(s[2*nb],   ah, bh); mma16816(s[2*nb+1], ah, bh + 2);
                mma16816(s[2*nb],   ah, bl); mma16816(s[2*nb+1], ah, bl + 2);
                mma16816(s[2*nb],   al, bh); mma16816(s[2*nb+1], al, bh + 2);
            }
        }
        #pragma unroll
        for (int i = 0; i < 8; i++)
            #pragma unroll
            for (int q = 0; q < 4; q++) s[i][q] *= 0.125f;

        // ---- online softmax ----
        float mx0 = -1e30f, mx1 = -1e30f;
        #pragma unroll
        for (int i = 0; i < 8; i++) {
            mx0 = fmaxf(mx0, fmaxf(s[i][0], s[i][1]));
            mx1 = fmaxf(mx1, fmaxf(s[i][2], s[i][3]));
        }
        mx0 = fmaxf(mx0, __shfl_xor_sync(0xFFFFFFFFu, mx0, 1));
        mx0 = fmaxf(mx0, __shfl_xor_sync(0xFFFFFFFFu, mx0, 2));
        mx1 = fmaxf(mx1, __shfl_xor_sync(0xFFFFFFFFu, mx1, 1));
        mx1 = fmaxf(mx1, __shfl_xor_sync(0xFFFFFFFFu, mx1, 2));
        float nm0 = fmaxf(m0, mx0), nm1 = fmaxf(m1, mx1);
        float sc0 = __expf(m0 - nm0), sc1 = __expf(m1 - nm1);
        m0 = nm0; m1 = nm1;

        float sum0 = 0.f, sum1 = 0.f;
        #pragma unroll
        for (int i = 0; i < 8; i++) {
            s[i][0] = __expf(s[i][0] - m0);
            s[i][1] = __expf(s[i][1] - m0);
            s[i][2] = __expf(s[i][2] - m1);
            s[i][3] = __expf(s[i][3] - m1);
            sum0 += s[i][0] + s[i][1];
            sum1 += s[i][2] + s[i][3];
        }
        sum0 += __shfl_xor_sync(0xFFFFFFFFu, sum0, 1);
        sum0 += __shfl_xor_sync(0xFFFFFFFFu, sum0, 2);
        sum1 += __shfl_xor_sync(0xFFFFFFFFu, sum1, 1);
        sum1 += __shfl_xor_sync(0xFFFFFFFFu, sum1, 2);
        rs0 = rs0 * sc0 + sum0;
        rs1 = rs1 * sc1 + sum1;

        #pragma unroll
        for (int i = 0; i < 8; i++) {
            o[i][0] *= sc0; o[i][1] *= sc0;
            o[i][2] *= sc1; o[i][3] *= sc1;
        }

        // ---- O += P @ V (V via ldmatrix.trans), split 3-pass ----
        #pragma unroll
        for (int kc = 0; kc < 4; kc++) {
            uint32_t ah[4], al[4];
            ah[0] = pkh(s[2*kc][0],   s[2*kc][1]);
            ah[1] = pkh(s[2*kc][2],   s[2*kc][3]);
            ah[2] = pkh(s[2*kc+1][0], s[2*kc+1][1]);
            ah[3] = pkh(s[2*kc+1][2], s[2*kc+1][3]);
            al[0] = pkl(s[2*kc][0],   s[2*kc][1]);
            al[1] = pkl(s[2*kc][2],   s[2*kc][3]);
            al[2] = pkl(s[2*kc+1][0], s[2*kc+1][1]);
            al[3] = pkl(s[2*kc+1][2], s[2*kc+1][3]);
            #pragma unroll
            for (int nb = 0; nb < 4; nb++) {
                uint32_t off = (kc*16 + (l & 15)) * 128 + nb*32 + ((l >> 4) * 16);
                uint32_t bh[4], bl[4];
                ldsm4t(bh, Vst + swz(off));
                ldsm4t(bl, Vst + 8192 + swz(off));
                mma16816(o[2*nb],   ah, bh); mma16816(o[2*nb+1], ah, bh + 2);
                mma16816(o[2*nb],   ah, bl); mma16816(o[2*nb+1], ah, bl + 2);
                mma16816(o[2*nb],   al, bh); mma16816(o[2*nb+1], al, bh + 2);
            }
        }

        __syncthreads();
        if (c + 2 < NCH) load_kv(c + 2, c & 1);
    }

    // ---- epilogue: x += O / rowsum ----
    const float inv0 = 1.f / rs0, inv1 = 1.f / rs1;
    const long tok0 = tokq + wid * 16 + (l >> 2);
    const long col = h * HD_ + (l & 3) * 2;
    #pragma unroll
    for (int nf = 0; nf < 8; nf++) {
        float2* p0 = (float2*)(x + tok0 * D_ + col + nf * 8);
        float2 t0 = *p0;
        t0.x += o[nf][0] * inv0; t0.y += o[nf][1] * inv0;
        *p0 = t0;
        float2* p1 = (float2*)(x + (tok0 + 8) * D_ + col + nf * 8);
        float2 t1 = *p1;
        t1.x += o[nf][2] * inv1; t1.y += o[nf][3] * inv1;
        *p1 = t1;
    }
}

// =================== driver ================================================
extern "C" void kernel_launch(void* const* d_in, const int* in_sizes, int n_in,
                              void* d_out, int out_size)
{
    const float* x0  = (const float*)d_in[0];
    const float* Wq  = (const float*)d_in[1];
    const float* bq  = (const float*)d_in[2];
    const float* Wk  = (const float*)d_in[3];
    const float* bk  = (const float*)d_in[4];
    const float* Wv  = (const float*)d_in[5];
    const float* bv  = (const float*)d_in[6];
    const float* g1  = (const float*)d_in[7];
    const float* be1 = (const float*)d_in[8];
    const float* g2  = (const float*)d_in[9];
    const float* be2 = (const float*)d_in[10];
    const float* W0  = (const float*)d_in[11];
    const float* b0  = (const float*)d_in[12];
    const float* W1  = (const float*)d_in[13];
    const float* b1  = (const float*)d_in[14];

    float* x = (float*)d_out;

    __nv_bfloat16 *lns, *qkvs, *ffs, *wqkv, *w0t, *w1t;
    float *bqkv, *ffw;
    cudaGetSymbolAddress((void**)&lns,  g_lns);
    cudaGetSymbolAddress((void**)&qkvs, g_qkvs);
    cudaGetSymbolAddress((void**)&ffs,  g_ffs);
    cudaGetSymbolAddress((void**)&ffw,  g_ffw);
    cudaGetSymbolAddress((void**)&wqkv, g_wqkv);
    cudaGetSymbolAddress((void**)&w0t,  g_w0t);
    cudaGetSymbolAddress((void**)&w1t,  g_w1t);
    cudaGetSymbolAddress((void**)&bqkv, g_bqkv);

    const int SMG = 3 * (128*128 + 128*128) + 256;   // 98560
    const int SMF = 32768 + 2 * 32768 + 256;          // 98560
    cudaFuncSetAttribute(gemm_mma<0>, cudaFuncAttributeMaxDynamicSharedMemorySize, SMG);
    cudaFuncSetAttribute(gemm_mma<3>, cudaFuncAttributeMaxDynamicSharedMemorySize, SMG);
    cudaFuncSetAttribute(gemm_mma<5>, cudaFuncAttributeMaxDynamicSharedMemorySize, SMG);
    cudaFuncSetAttribute(flash_attn,  cudaFuncAttributeMaxDynamicSharedMemorySize, SMF);

    cudaMemcpyAsync(x, x0, sizeof(float)*M_*D_, cudaMemcpyDeviceToDevice);

    // ---- weight preprocessing: 3 launches, so launch #5 = QKV GEMM (ncu -s 5) ----
    dim3 tb(32, 8);
    tsplit_qkv<<<dim3(D_/32, D_/32, 3), tb>>>(Wq, Wk, Wv, wqkv);        // launch 1
    tsplit_mlp<<<dim3(F_/32, D_/32, 2), tb>>>(W0, W1, w0t, w1t);        // launch 2
    cat_bias<<<9, 256>>>(bq, bk, bv, bqkv);                             // launch 3

    const long MD   = (long)M_ * D_;
    const long MQ   = (long)M_ * QKVN;
    const long MF   = (long)M_ * F_;
    const long WDF  = (long)D_ * F_;
    const long WQKV = (long)QKVN * D_;

    for (int blk = 0; blk < NBLOCKS; blk++) {
        // ---- attention ----
        ln_kernel<<<M_/8, 256>>>(x, g1, be1, lns, MD);                  // launch 4 (blk 0)

        gemm_mma<3><<<dim3(QKVN/128, M_/128), 256, SMG>>>(              // launch 5 (blk 0)
            lns, wqkv, bqkv, qkvs, D_, D_, D_, QKVN, MD, WQKV, MQ);

        flash_attn<<<dim3(N_/128, B_*H_), 256, SMF>>>(qkvs, x, MQ);

        // ---- MLP ----
        ln_kernel<<<M_/8, 256>>>(x, g2, be2, lns, MD);

        // MLP1: split-K x3 into three fp32 buffers (4 dense waves of 296)
        gemm_mma<0><<<dim3(F_/128, M_/128, 3), 256, SMG>>>(
            lns, w0t, nullptr, ffw, D_/3, D_, D_, F_, MD, WDF, MF);

        // combine + bias + GELU + split
        gelu_split<<<(int)(MF/1024), 256>>>(ffw, ffw + MF, ffw + 2*MF, b0, ffs, MF);

        // MLP2: split-K x3 (288 CTAs = one full wave), atomic residual into x
        gemm_mma<5><<<dim3(D_/128, M_/128, 3), 256, SMG>>>(
            ffs, w1t, b1, x, F_/3, F_, F_, D_, MF, WDF, 0);
    }
    (void)in_sizes; (void)n_in; (void)out_size;
}

// round 9
// speedup vs baseline: 4.3534x; 1.0025x over previous
#include <cuda_runtime.h>
#include <cuda_bf16.h>
#include <math.h>
#include <stdint.h>

// Problem constants
#define B_  4
#define N_  512
#define D_  768
#define F_  3072
#define H_  12
#define HD_ 64
#define M_  (B_*N_)   // 2048 tokens
#define NBLOCKS 12
#define QKVN (3*D_)   // 2304

// =================== scratch (static device globals) ========================
__device__ __align__(256) __nv_bfloat16 g_lns [2L*M_*D_];
__device__ __align__(256) __nv_bfloat16 g_qkvs[2L*M_*QKVN];
__device__ __align__(256) __nv_bfloat16 g_ffs [2L*M_*F_];
__device__ __align__(256) float         g_ffw [3L*M_*F_];   // split-K fp32 partials
__device__ __align__(256) __nv_bfloat16 g_wqkv[2L*QKVN*D_];
__device__ __align__(256) __nv_bfloat16 g_w0t [2L*D_*F_];
__device__ __align__(256) __nv_bfloat16 g_w1t [2L*D_*F_];
__device__ float g_bqkv[QKVN];

// =================== PTX helpers ===========================================
__device__ __forceinline__ uint32_t smem_u32(const void* p){
    uint32_t a;
    asm("{ .reg .u64 t; cvta.to.shared.u64 t, %1; cvt.u32.u64 %0, t; }" : "=r"(a) : "l"(p));
    return a;
}
__device__ __forceinline__ void cpa16(uint32_t d, const void* s){
    asm volatile("cp.async.cg.shared.global [%0], [%1], 16;" :: "r"(d), "l"(s));
}
#define CP_COMMIT() asm volatile("cp.async.commit_group;" ::: "memory")

__device__ __forceinline__ void ldsm4(uint32_t* r, uint32_t addr){
    asm volatile("ldmatrix.sync.aligned.m8n8.x4.shared.b16 {%0,%1,%2,%3}, [%4];"
                 : "=r"(r[0]), "=r"(r[1]), "=r"(r[2]), "=r"(r[3]) : "r"(addr));
}
__device__ __forceinline__ void ldsm4t(uint32_t* r, uint32_t addr){
    asm volatile("ldmatrix.sync.aligned.m8n8.x4.trans.shared.b16 {%0,%1,%2,%3}, [%4];"
                 : "=r"(r[0]), "=r"(r[1]), "=r"(r[2]), "=r"(r[3]) : "r"(addr));
}
__device__ __forceinline__ void mma16816(float* c, const uint32_t* a, const uint32_t* b){
    asm volatile(
        "mma.sync.aligned.m16n8k16.row.col.f32.bf16.bf16.f32 "
        "{%0,%1,%2,%3}, {%4,%5,%6,%7}, {%8,%9}, {%0,%1,%2,%3};"
        : "+f"(c[0]), "+f"(c[1]), "+f"(c[2]), "+f"(c[3])
        : "r"(a[0]), "r"(a[1]), "r"(a[2]), "r"(a[3]), "r"(b[0]), "r"(b[1]));
}
__device__ __forceinline__ void redg2(float* p, float a, float b){
    asm volatile("red.global.v2.f32.add [%0], {%1, %2};" :: "l"(p), "f"(a), "f"(b) : "memory");
}
__device__ __forceinline__ float gelu_exact(float v){
    return 0.5f * v * (1.0f + erff(v * 0.70710678118654752f));
}
__device__ __forceinline__ uint32_t swz(uint32_t off){ return off ^ ((off >> 3) & 0x70); }
__device__ __forceinline__ uint32_t pkh(float x, float y){
    __nv_bfloat162 h; h.x = __float2bfloat16(x); h.y = __float2bfloat16(y);
    return *(uint32_t*)&h;
}
__device__ __forceinline__ uint32_t pkl(float x, float y){
    float rx = x - __bfloat162float(__float2bfloat16(x));
    float ry = y - __bfloat162float(__float2bfloat16(y));
    __nv_bfloat162 h; h.x = __float2bfloat16(rx); h.y = __float2bfloat16(ry);
    return *(uint32_t*)&h;
}

// =================== LayerNorm: warp per row, 4 rows/CTA ====================
__global__ void __launch_bounds__(128)
ln_kernel(const float* __restrict__ x,
          const float* __restrict__ g,
          const float* __restrict__ be,
          __nv_bfloat16* __restrict__ out, long plane)
{
    const int w = threadIdx.x >> 5, l = threadIdx.x & 31;
    const long row = (long)blockIdx.x * 4 + w;
    const float* xr = x + row * D_;

    float4 v[6];
    float s = 0.f;
    #pragma unroll
    for (int i = 0; i < 6; i++) {
        v[i] = *(const float4*)(xr + i * 128 + l * 4);
        s += v[i].x + v[i].y + v[i].z + v[i].w;
    }
    #pragma unroll
    for (int o = 16; o > 0; o >>= 1) s += __shfl_xor_sync(0xFFFFFFFFu, s, o);
    const float mu = s * (1.0f / D_);

    float vs = 0.f;
    #pragma unroll
    for (int i = 0; i < 6; i++) {
        float a = v[i].x - mu, b2 = v[i].y - mu, c = v[i].z - mu, d = v[i].w - mu;
        vs += a*a + b2*b2 + c*c + d*d;
    }
    #pragma unroll
    for (int o = 16; o > 0; o >>= 1) vs += __shfl_xor_sync(0xFFFFFFFFu, vs, o);
    const float inv = rsqrtf(vs * (1.0f / D_) + 1e-5f);

    __nv_bfloat16* orow = out + row * D_;
    #pragma unroll
    for (int i = 0; i < 6; i++) {
        const int col = i * 128 + l * 4;
        float4 gg = *(const float4*)(g  + col);
        float4 bb = *(const float4*)(be + col);
        float y0 = (v[i].x - mu) * inv * gg.x + bb.x;
        float y1 = (v[i].y - mu) * inv * gg.y + bb.y;
        float y2 = (v[i].z - mu) * inv * gg.z + bb.z;
        float y3 = (v[i].w - mu) * inv * gg.w + bb.w;
        uint2 hp; hp.x = pkh(y0, y1); hp.y = pkh(y2, y3);
        *(uint2*)(orow + col) = hp;
        uint2 lp; lp.x = pkl(y0, y1); lp.y = pkl(y2, y3);
        *(uint2*)(orow + plane + col) = lp;
    }
}

// =================== Weight transpose + split (batched) =====================
__device__ __forceinline__ void tsplit_tile(const float* __restrict__ in,
                                            __nv_bfloat16* __restrict__ out,
                                            int ldin, int ldout, long plane,
                                            int c0, int r0, int tx, int ty,
                                            float (*t)[33])
{
    #pragma unroll
    for (int i = 0; i < 32; i += 8)
        t[ty+i][tx] = in[(long)(r0+ty+i) * ldin + c0 + tx];
    __syncthreads();
    #pragma unroll
    for (int i = 0; i < 32; i += 8) {
        float v = t[tx][ty+i];
        __nv_bfloat16 h = __float2bfloat16(v);
        long o = (long)(c0+ty+i) * ldout + r0 + tx;
        out[o] = h;
        out[o + plane] = __float2bfloat16(v - __bfloat162float(h));
    }
}

// launch 1: Wq/Wk/Wv (z = 0/1/2), each [D_, D_] -> wqkv + z*D_*D_
__global__ void tsplit_qkv(const float* __restrict__ Wq, const float* __restrict__ Wk,
                           const float* __restrict__ Wv, __nv_bfloat16* __restrict__ out)
{
    __shared__ float t[32][33];
    const int z = blockIdx.z;
    const float* in = (z == 0) ? Wq : (z == 1) ? Wk : Wv;
    tsplit_tile(in, out + (long)z * D_ * D_, D_, D_, (long)QKVN * D_,
                blockIdx.x * 32, blockIdx.y * 32, threadIdx.x, threadIdx.y, t);
}

// launch 2: W0 (z=0), W1 (z=1), bias concat (z=2, one row of blocks)
__global__ void tsplit_mlp(const float* __restrict__ W0, const float* __restrict__ W1,
                           __nv_bfloat16* __restrict__ w0t, __nv_bfloat16* __restrict__ w1t,
                           const float* __restrict__ bq, const float* __restrict__ bk,
                           const float* __restrict__ bv, float* __restrict__ bqkv)
{
    __shared__ float t[32][33];
    const int z = blockIdx.z;
    if (z == 2) {
        if (blockIdx.y == 0) {
            int i = blockIdx.x * 256 + threadIdx.y * 32 + threadIdx.x;
            if (i < QKVN)
                bqkv[i] = (i < D_) ? bq[i] : (i < 2*D_) ? bk[i - D_] : bv[i - 2*D_];
        }
        return;
    }
    const int bx = z ? blockIdx.y : blockIdx.x;
    const int by = z ? blockIdx.x : blockIdx.y;
    if (z == 0)
        tsplit_tile(W0, w0t, F_, D_, (long)D_ * F_, bx * 32, by * 32,
                    threadIdx.x, threadIdx.y, t);
    else
        tsplit_tile(W1, w1t, D_, F_, (long)D_ * F_, bx * 32, by * 32,
                    threadIdx.x, threadIdx.y, t);
}

// =================== GELU + split combine (MLP1 split-K x3) =================
__global__ void __launch_bounds__(256)
gelu_split(const float* __restrict__ a, const float* __restrict__ b,
           const float* __restrict__ c,
           const float* __restrict__ bias, __nv_bfloat16* __restrict__ out, long plane)
{
    const long i0 = ((long)blockIdx.x * 256 + threadIdx.x) * 4;
    const int col = (int)(i0 % F_);
    float4 va = *(const float4*)(a + i0);
    float4 vb = *(const float4*)(b + i0);
    float4 vc = *(const float4*)(c + i0);
    float4 bs = *(const float4*)(bias + col);
    float y0 = gelu_exact(va.x + vb.x + vc.x + bs.x);
    float y1 = gelu_exact(va.y + vb.y + vc.y + bs.y);
    float y2 = gelu_exact(va.z + vb.z + vc.z + bs.z);
    float y3 = gelu_exact(va.w + vb.w + vc.w + bs.w);
    uint2 hp; hp.x = pkh(y0, y1); hp.y = pkh(y2, y3);
    *(uint2*)(out + i0) = hp;
    uint2 lp; lp.x = pkl(y0, y1); lp.y = pkl(y2, y3);
    *(uint2*)(out + plane + i0) = lp;
}

// =================== HMMA GEMM, 3-stage pipeline, 2 CTAs/SM ================
// EPI 0: fp32 C[z-buffer] = v | EPI 3: split-bf16 C = v + bias
// EPI 5: fp32 red.add(C, v [+ bias if z==0])
template<int EPI>
__global__ void __launch_bounds__(256, 2)
gemm_mma(const __nv_bfloat16* __restrict__ A, const __nv_bfloat16* __restrict__ B,
         const float* __restrict__ bias, void* __restrict__ Cv,
         int K, int lda, int ldb, int ldc,
         long planeA, long planeB, long planeC)
{
    extern __shared__ char sm[];
    constexpr int ABYTES = 128 * 128;
    constexpr int BBYTES = 128 * 128;
    constexpr int STG = ABYTES + BBYTES;

    const uint32_t smb = (smem_u32(sm) + 127) & ~127u;

    const int tid = threadIdx.x;
    const int wid = tid >> 5, l = tid & 31;
    const int wm = (wid & 3) * 32;
    const int wn = (wid >> 2) * 64;

    const long bm = (long)blockIdx.y * 128;
    const long bn = (long)blockIdx.x * 128;
    const long koff = (long)blockIdx.z * K;

    float* Cf = (float*)Cv;
    if (EPI == 0) Cf += (long)blockIdx.z * planeC;
    __nv_bfloat16* Cb = (__nv_bfloat16*)Cv;

    const int kch = K / 64;
    const int NC = 3 * kch;

    float acc[2][8][4];
    #pragma unroll
    for (int i = 0; i < 2; i++)
        #pragma unroll
        for (int j = 0; j < 8; j++)
            #pragma unroll
            for (int q = 0; q < 4; q++) acc[i][j][q] = 0.f;

    auto load_chunk = [&](int c, int st) {
        const int p  = c / kch;
        const long kk = koff + (long)(c - p * kch) * 64;
        const __nv_bfloat16* Ap = A + ((p == 2) ? planeA : 0) + kk;
        const __nv_bfloat16* Bp = B + ((p == 1) ? planeB : 0) + kk;
        const uint32_t sA = smb + st * STG;
        const uint32_t sB = sA + ABYTES;
        #pragma unroll
        for (int j = 0; j < 4; j++) {
            int idx = tid * 4 + j;
            int row = idx >> 3, c16 = (idx & 7) * 16;
            cpa16(sA + swz(row * 128 + c16),
                  (const char*)(Ap + (bm + row) * lda) + c16);
        }
        #pragma unroll
        for (int j = 0; j < 4; j++) {
            int idx = tid * 4 + j;
            int row = idx >> 3, c16 = (idx & 7) * 16;
            cpa16(sB + swz(row * 128 + c16),
                  (const char*)(Bp + (bn + row) * ldb) + c16);
        }
        CP_COMMIT();
    };

    auto compute = [&](int st) {
        const uint32_t bA = smb + st * STG;
        const uint32_t bB = bA + ABYTES;
        #pragma unroll
        for (int kk2 = 0; kk2 < 4; kk2++) {
            uint32_t a[2][4];
            #pragma unroll
            for (int tm = 0; tm < 2; tm++) {
                int row = wm + tm * 16 + (l & 15);
                uint32_t off = row * 128 + kk2 * 32 + ((l >> 4) * 16);
                ldsm4(a[tm], bA + swz(off));
            }
            #pragma unroll
            for (int nb = 0; nb < 4; nb++) {
                uint32_t b[4];
                int rowB = wn + nb * 16 + (l & 7) + ((l >> 4) << 3);
                uint32_t off = rowB * 128 + kk2 * 32 + (((l >> 3) & 1) * 16);
                ldsm4(b, bB + swz(off));
                #pragma unroll
                for (int tm = 0; tm < 2; tm++) {
                    mma16816(acc[tm][2*nb],   a[tm], b);
                    mma16816(acc[tm][2*nb+1], a[tm], b + 2);
                }
            }
        }
    };

    load_chunk(0, 0);
    load_chunk(1, 1);
    for (int c = 0; c < NC; c++) {
        if (c < NC - 1) asm volatile("cp.async.wait_group 1;" ::: "memory");
        else            asm volatile("cp.async.wait_group 0;" ::: "memory");
        __syncthreads();
        if (c + 2 < NC) load_chunk(c + 2, (c + 2) % 3);
        compute(c % 3);
    }

    // -------- epilogue --------
    const bool addb = (EPI != 5) || (blockIdx.z == 0);
    #pragma unroll
    for (int tm = 0; tm < 2; tm++) {
        #pragma unroll
        for (int nf = 0; nf < 8; nf++) {
            const long col = bn + wn + nf * 8 + (l & 3) * 2;
            const float bb0 = (bias && addb) ? bias[col]     : 0.f;
            const float bb1 = (bias && addb) ? bias[col + 1] : 0.f;
            #pragma unroll
            for (int h = 0; h < 2; h++) {
                const long row = bm + wm + tm * 16 + (l >> 2) + h * 8;
                float v0 = acc[tm][nf][2*h]     + bb0;
                float v1 = acc[tm][nf][2*h + 1] + bb1;
                const long idx = row * (long)ldc + col;
                if (EPI == 0) {
                    float2 t; t.x = v0; t.y = v1;
                    *(float2*)(Cf + idx) = t;
                } else if (EPI == 5) {
                    redg2(Cf + idx, v0, v1);
                } else {
                    __nv_bfloat16 h0 = __float2bfloat16(v0);
                    __nv_bfloat16 h1 = __float2bfloat16(v1);
                    __nv_bfloat162 hv; hv.x = h0; hv.y = h1;
                    *(__nv_bfloat162*)(Cb + idx) = hv;
                    __nv_bfloat162 lv;
                    lv.x = __float2bfloat16(v0 - __bfloat162float(h0));
                    lv.y = __float2bfloat16(v1 - __bfloat162float(h1));
                    *(__nv_bfloat162*)(Cb + idx + planeC) = lv;
                }
            }
        }
    }
}

// =================== Fused flash attention =================================
__global__ void __launch_bounds__(256, 2)
flash_attn(const __nv_bfloat16* __restrict__ qkv, float* __restrict__ x, long planeQ)
{
    extern __shared__ char sm[];
    const uint32_t smb = (smem_u32(sm) + 127) & ~127u;
    const uint32_t Qb = smb;             // Q: hi 16K + lo 16K
    const uint32_t St = smb + 32768;     // 2 stages x 32K

    const int tid = threadIdx.x, wid = tid >> 5, l = tid & 31;
    const int qt = blockIdx.x, z = blockIdx.y;
    const int b = z / H_, h = z % H_;
    const long tokq = (long)b * N_ + qt * 128;

    #pragma unroll
    for (int p = 0; p < 2; p++)
        #pragma unroll
        for (int j = 0; j < 4; j++) {
            int idx = tid * 4 + j;
            int row = idx >> 3, c16 = idx & 7;
            cpa16(Qb + p*16384 + swz(row*128 + c16*16),
                  qkv + p*planeQ + (tokq + row)*QKVN + h*HD_ + c16*8);
        }

    auto load_kv = [&](int c, int st) {
        const uint32_t base = St + st * 32768;
        #pragma unroll
        for (int p = 0; p < 2; p++)
            #pragma unroll
            for (int j = 0; j < 2; j++) {
                int idx = tid * 2 + j;
                int row = idx >> 3, c16 = idx & 7;
                const long tok = (long)b * N_ + c * 64 + row;
                cpa16(base + p*8192 + swz(row*128 + c16*16),
                      qkv + p*planeQ + tok*QKVN + D_ + h*HD_ + c16*8);
                cpa16(base + 16384 + p*8192 + swz(row*128 + c16*16),
                      qkv + p*planeQ + tok*QKVN + 2*D_ + h*HD_ + c16*8);
            }
        CP_COMMIT();
    };

    load_kv(0, 0);
    load_kv(1, 1);

    float o[8][4];
    #pragma unroll
    for (int i = 0; i < 8; i++)
        #pragma unroll
        for (int q = 0; q < 4; q++) o[i][q] = 0.f;
    float m0 = -1e30f, m1 = -1e30f, rs0 = 0.f, rs1 = 0.f;

    const int NCH = N_ / 64;   // 8
    for (int c = 0; c < NCH; c++) {
        if (c < NCH - 1) asm volatile("cp.async.wait_group 1;" ::: "memory");
        else             asm volatile("cp.async.wait_group 0;" ::: "memory");
        __syncthreads();

        const uint32_t Kst = St + (c & 1) * 32768;
        const uint32_t Vst = Kst + 16384;

        float s[8][4];
        #pragma unroll
        for (int i = 0; i < 8; i++)
            #pragma unroll
            for (int q = 0; q < 4; q++) s[i][q] = 0.f;

        #pragma unroll
        for (int kk = 0; kk < 4; kk++) {
            uint32_t ah[4], al[4];
            {
                int row = wid * 16 + (l & 15);
                uint32_t off = row * 128 + kk * 32 + ((l >> 4) * 16);
                ldsm4(ah, Qb + swz(off));
                ldsm4(al, Qb + 16384 + swz(off));
            }
            #pragma unroll
            for (int nb = 0; nb < 4; nb++) {
                int rowB = nb * 16 + (l & 7) + ((l >> 4) << 3);
                uint32_t off = rowB * 128 + kk * 32 + (((l >> 3) & 1) * 16);
                uint32_t bh[4], bl[4];
                ldsm4(bh, Kst + swz(off));
                ldsm4(bl, Kst + 8192 + swz(off));
                mma16816(s[2*nb],   ah, bh); mma16816(s[2*nb+1], ah, bh + 2);
                mma16816(s[2*nb],   ah, bl); mma16816(s[2*nb+1], ah, bl + 2);
                mma16816(s[2*nb],   al, bh); mma16816(s[2*nb+1], al, bh + 2);
            }
        }
        #pragma unroll
        for (int i = 0; i < 8; i++)
            #pragma unroll
            for (int q = 0; q < 4; q++) s[i][q] *= 0.125f;

        float mx0 = -1e30f, mx1 = -1e30f;
        #pragma unroll
        for (int i = 0; i < 8; i++) {
            mx0 = fmaxf(mx0, fmaxf(s[i][0], s[i][1]));
            mx1 = fmaxf(mx1, fmaxf(s[i][2], s[i][3]));
        }
        mx0 = fmaxf(mx0, __shfl_xor_sync(0xFFFFFFFFu, mx0, 1));
        mx0 = fmaxf(mx0, __shfl_xor_sync(0xFFFFFFFFu, mx0, 2));
        mx1 = fmaxf(mx1, __shfl_xor_sync(0xFFFFFFFFu, mx1, 1));
        mx1 = fmaxf(mx1, __shfl_xor_sync(0xFFFFFFFFu, mx1, 2));
        float nm0 = fmaxf(m0, mx0), nm1 = fmaxf(m1, mx1);
        float sc0 = __expf(m0 - nm0), sc1 = __expf(m1 - nm1);
        m0 = nm0; m1 = nm1;

        float sum0 = 0.f, sum1 = 0.f;
        #pragma unroll
        for (int i = 0; i < 8; i++) {
            s[i][0] = __expf(s[i][0] - m0);
            s[i][1] = __expf(s[i][1] - m0);
            s[i][2] = __expf(s[i][2] - m1);
            s[i][3] = __expf(s[i][3] - m1);
            sum0 += s[i][0] + s[i][1];
            sum1 += s[i][2] + s[i][3];
        }
        sum0 += __shfl_xor_sync(0xFFFFFFFFu, sum0, 1);
        sum0 += __shfl_xor_sync(0xFFFFFFFFu, sum0, 2);
        sum1 += __shfl_xor_sync(0xFFFFFFFFu, sum1, 1);
        sum1 += __shfl_xor_sync(0xFFFFFFFFu, sum1, 2);
        rs0 = rs0 * sc0 + sum0;
        rs1 = rs1 * sc1 + sum1;

        #pragma unroll
        for (int i = 0; i < 8; i++) {
            o[i][0] *= sc0; o[i][1] *= sc0;
            o[i][2] *= sc1; o[i][3] *= sc1;
        }

        #pragma unroll
        for (int kc = 0; kc < 4; kc++) {
            uint32_t ah[4], al[4];
            ah[0] = pkh(s[2*kc][0],   s[2*kc][1]);
            ah[1] = pkh(s[2*kc][2],   s[2*kc][3]);
            ah[2] = pkh(s[2*kc+1][0], s[2*kc+1][1]);
            ah[3] = pkh(s[2*kc+1][2], s[2*kc+1][3]);
            al[0] = pkl(s[2*kc][0],   s[2*kc][1]);
            al[1] = pkl(s[2*kc][2],   s[2*kc][3]);
            al[2] = pkl(s[2*kc+1][0], s[2*kc+1][1]);
            al[3] = pkl(s[2*kc+1][2], s[2*kc+1][3]);
            #pragma unroll
            for (int nb = 0; nb < 4; nb++) {
                uint32_t off = (kc*16 + (l & 15)) * 128 + nb*32 + ((l >> 4) * 16);
                uint32_t bh[4], bl[4];
                ldsm4t(bh, Vst + swz(off));
                ldsm4t(bl, Vst + 8192 + swz(off));
                mma16816(o[2*nb],   ah, bh); mma16816(o[2*nb+1], ah, bh + 2);
                mma16816(o[2*nb],   ah, bl); mma16816(o[2*nb+1], ah, bl + 2);
                mma16816(o[2*nb],   al, bh); mma16816(o[2*nb+1], al, bh + 2);
            }
        }

        __syncthreads();
        if (c + 2 < NCH) load_kv(c + 2, c & 1);
    }

    const float inv0 = 1.f / rs0, inv1 = 1.f / rs1;
    const long tok0 = tokq + wid * 16 + (l >> 2);
    const long col = h * HD_ + (l & 3) * 2;
    #pragma unroll
    for (int nf = 0; nf < 8; nf++) {
        float2* p0 = (float2*)(x + tok0 * D_ + col + nf * 8);
        float2 t0 = *p0;
        t0.x += o[nf][0] * inv0; t0.y += o[nf][1] * inv0;
        *p0 = t0;
        float2* p1 = (float2*)(x + (tok0 + 8) * D_ + col + nf * 8);
        float2 t1 = *p1;
        t1.x += o[nf][2] * inv1; t1.y += o[nf][3] * inv1;
        *p1 = t1;
    }
}

// =================== driver ================================================
extern "C" void kernel_launch(void* const* d_in, const int* in_sizes, int n_in,
                              void* d_out, int out_size)
{
    const float* x0  = (const float*)d_in[0];
    const float* Wq  = (const float*)d_in[1];
    const float* bq  = (const float*)d_in[2];
    const float* Wk  = (const float*)d_in[3];
    const float* bk  = (const float*)d_in[4];
    const float* Wv  = (const float*)d_in[5];
    const float* bv  = (const float*)d_in[6];
    const float* g1  = (const float*)d_in[7];
    const float* be1 = (const float*)d_in[8];
    const float* g2  = (const float*)d_in[9];
    const float* be2 = (const float*)d_in[10];
    const float* W0  = (const float*)d_in[11];
    const float* b0  = (const float*)d_in[12];
    const float* W1  = (const float*)d_in[13];
    const float* b1  = (const float*)d_in[14];

    float* x = (float*)d_out;

    __nv_bfloat16 *lns, *qkvs, *ffs, *wqkv, *w0t, *w1t;
    float *bqkv, *ffw;
    cudaGetSymbolAddress((void**)&lns,  g_lns);
    cudaGetSymbolAddress((void**)&qkvs, g_qkvs);
    cudaGetSymbolAddress((void**)&ffs,  g_ffs);
    cudaGetSymbolAddress((void**)&ffw,  g_ffw);
    cudaGetSymbolAddress((void**)&wqkv, g_wqkv);
    cudaGetSymbolAddress((void**)&w0t,  g_w0t);
    cudaGetSymbolAddress((void**)&w1t,  g_w1t);
    cudaGetSymbolAddress((void**)&bqkv, g_bqkv);

    const int SMG = 3 * (128*128 + 128*128) + 256;   // 98560
    const int SMF = 32768 + 2 * 32768 + 256;          // 98560
    cudaFuncSetAttribute(gemm_mma<0>, cudaFuncAttributeMaxDynamicSharedMemorySize, SMG);
    cudaFuncSetAttribute(gemm_mma<3>, cudaFuncAttributeMaxDynamicSharedMemorySize, SMG);
    cudaFuncSetAttribute(gemm_mma<5>, cudaFuncAttributeMaxDynamicSharedMemorySize, SMG);
    cudaFuncSetAttribute(flash_attn,  cudaFuncAttributeMaxDynamicSharedMemorySize, SMF);

    cudaMemcpyAsync(x, x0, sizeof(float)*M_*D_, cudaMemcpyDeviceToDevice);

    // ---- weight preprocessing: 2 launches so captured #4 = QKV GEMM ----
    dim3 tb(32, 8);
    tsplit_qkv<<<dim3(D_/32, D_/32, 3), tb>>>(Wq, Wk, Wv, wqkv);                 // 1
    tsplit_mlp<<<dim3(F_/32, D_/32, 3), tb>>>(W0, W1, w0t, w1t, bq, bk, bv, bqkv); // 2

    const long MD   = (long)M_ * D_;
    const long MQ   = (long)M_ * QKVN;
    const long MF   = (long)M_ * F_;
    const long WDF  = (long)D_ * F_;
    const long WQKV = (long)QKVN * D_;

    for (int blk = 0; blk < NBLOCKS; blk++) {
        // ---- attention ----
        ln_kernel<<<M_/4, 128>>>(x, g1, be1, lns, MD);                   // 3 (blk 0)

        gemm_mma<3><<<dim3(QKVN/128, M_/128), 256, SMG>>>(               // 4 (blk 0) <- ncu
            lns, wqkv, bqkv, qkvs, D_, D_, D_, QKVN, MD, WQKV, MQ);

        flash_attn<<<dim3(N_/128, B_*H_), 256, SMF>>>(qkvs, x, MQ);

        // ---- MLP ----
        ln_kernel<<<M_/4, 128>>>(x, g2, be2, lns, MD);

        // MLP1: split-K x3 into three fp32 buffers (4 dense waves of 296)
        gemm_mma<0><<<dim3(F_/128, M_/128, 3), 256, SMG>>>(
            lns, w0t, nullptr, ffw, D_/3, D_, D_, F_, MD, WDF, MF);

        gelu_split<<<(int)(MF/1024), 256>>>(ffw, ffw + MF, ffw + 2*MF, b0, ffs, MF);

        // MLP2: split-K x3 (288 CTAs = one full wave), red.add residual into x
        gemm_mma<5><<<dim3(D_/128, M_/128, 3), 256, SMG>>>(
            ffs, w1t, b1, x, F_/3, F_, F_, D_, MF, WDF, 0);
    }
    (void)in_sizes; (void)n_in; (void)out_size;
}